// round 13
// baseline (speedup 1.0000x reference)
#include <cuda_runtime.h>
#include <cuda_bf16.h>
#include <math.h>
#include <stdint.h>

#define NMAX 20000
#define EMAX 320000
#define DD   256
#define HH   8
#define HDD  32
#define TEE  3
#define TNN  4
#define LLAY 3
#define FF   1024
#define NPB  8

// ---------------- scratch (device globals; zero-initialized at load) --------
__device__ float g_x   [NMAX*DD];
__device__ float g_KV  [NMAX*2*DD];
__device__ float g_QW  [NMAX*TEE*DD];
__device__ int   g_rowptr[NMAX+1];
__device__ int   g_cursor[NMAX];
__device__ int   g_cpack [EMAX];
__device__ int   g_order [NMAX];
__device__ int   g_tcnt  [TNN];
__device__ int   g_tcur  [TNN];
__device__ float g_WET [LLAY*TEE*HH*HDD*HDD];

__device__ __nv_bfloat16 g_aggH[NMAX*DD];
__device__ __nv_bfloat16 g_aggL[NMAX*DD];
__device__ __nv_bfloat16 g_xH  [NMAX*DD];
__device__ __nv_bfloat16 g_xL  [NMAX*DD];
__device__ __nv_bfloat16 g_ffnH[NMAX*FF];
__device__ __nv_bfloat16 g_ffnL[NMAX*FF];

__device__ __nv_bfloat16 g_WoT_hi[LLAY*DD*DD];
__device__ __nv_bfloat16 g_WoT_lo[LLAY*DD*DD];
__device__ __nv_bfloat16 g_W1T_hi[LLAY*FF*DD];
__device__ __nv_bfloat16 g_W1T_lo[LLAY*FF*DD];
__device__ __nv_bfloat16 g_W2T_hi[LLAY*DD*FF];
__device__ __nv_bfloat16 g_W2T_lo[LLAY*DD*FF];

// ---------------- helpers ------------------------------------------------
__device__ __forceinline__ float gelu_f(float v) {
    return 0.5f * v * (1.0f + erff(v * 0.70710678118654752f));
}
__device__ __forceinline__ uint32_t smem_to_u32(const void* p) {
    uint32_t a;
    asm("{ .reg .u64 t; cvta.to.shared.u64 t, %1; cvt.u32.u64 %0, t; }" : "=r"(a) : "l"(p));
    return a;
}
__device__ __forceinline__ void ldmat_x4(uint32_t* r, uint32_t addr) {
    asm volatile("ldmatrix.sync.aligned.m8n8.x4.shared.b16 {%0,%1,%2,%3}, [%4];"
        : "=r"(r[0]), "=r"(r[1]), "=r"(r[2]), "=r"(r[3]) : "r"(addr));
}
__device__ __forceinline__ void mma_bf16(float* d, const uint32_t* a, const uint32_t* b) {
    asm volatile("mma.sync.aligned.m16n8k16.row.col.f32.bf16.bf16.f32 "
        "{%0,%1,%2,%3}, {%4,%5,%6,%7}, {%8,%9}, {%0,%1,%2,%3};"
        : "+f"(d[0]), "+f"(d[1]), "+f"(d[2]), "+f"(d[3])
        : "r"(a[0]), "r"(a[1]), "r"(a[2]), "r"(a[3]), "r"(b[0]), "r"(b[1]));
}
__device__ __forceinline__ void cp16z(uint32_t dst, const void* src, bool valid) {
    int sz = valid ? 16 : 0;
    asm volatile("cp.async.cg.shared.global [%0], [%1], 16, %2;"
        :: "r"(dst), "l"(src), "r"(sz));
}
#define CP_COMMIT()  asm volatile("cp.async.commit_group;" ::: "memory")
#define CP_WAIT1()   asm volatile("cp.async.wait_group 1;" ::: "memory")
#define CP_WAIT0()   asm volatile("cp.async.wait_group 0;" ::: "memory")

__device__ __forceinline__ void split_bf16(float v, __nv_bfloat16& h, __nv_bfloat16& l) {
    h = __float2bfloat16_rn(v);
    l = __float2bfloat16_rn(v - __bfloat162float(h));
}

// ======= preprocessing (3 launches) ===========================================
__device__ __forceinline__ void splitT_one(const float* W, __nv_bfloat16* hi,
                                           __nv_bfloat16* lo, int K, int N, int i) {
    int k = i / N, n = i % N;
    float w = W[i];
    __nv_bfloat16 h, l; split_bf16(w, h, l);
    hi[(size_t)n * K + k] = h;
    lo[(size_t)n * K + k] = l;
}

__global__ void k_count(const int* __restrict__ ei, const int* __restrict__ nt,
                        const float* __restrict__ WE, const float* __restrict__ Wo,
                        const float* __restrict__ w1, const float* __restrict__ w2,
                        int n, int E) {
    int gs = gridDim.x * blockDim.x;
    int gid = blockIdx.x * blockDim.x + threadIdx.x;
    for (int i = gid; i < E; i += gs) atomicAdd(&g_cursor[ei[E + i]], 1);
    for (int i = gid; i < n; i += gs) atomicAdd(&g_tcnt[nt[i]], 1);
    for (int i = gid; i < LLAY * TEE * HH * HDD * HDD; i += gs) {
        int d = i & 31, e = (i >> 5) & 31, base = i >> 10;
        g_WET[i] = WE[(base << 10) + (d << 5) + e];
    }
    for (int i = gid; i < LLAY * DD * DD; i += gs) {
        int l = i / (DD * DD), j = i % (DD * DD);
        splitT_one(Wo + (size_t)l * DD * DD, g_WoT_hi + (size_t)l * DD * DD,
                   g_WoT_lo + (size_t)l * DD * DD, DD, DD, j);
    }
    for (int i = gid; i < LLAY * DD * FF; i += gs) {
        int l = i / (DD * FF), j = i % (DD * FF);
        splitT_one(w1 + (size_t)l * DD * FF, g_W1T_hi + (size_t)l * FF * DD,
                   g_W1T_lo + (size_t)l * FF * DD, DD, FF, j);
    }
    for (int i = gid; i < LLAY * FF * DD; i += gs) {
        int l = i / (FF * DD), j = i % (FF * DD);
        splitT_one(w2 + (size_t)l * FF * DD, g_W2T_hi + (size_t)l * DD * FF,
                   g_W2T_lo + (size_t)l * DD * FF, FF, DD, j);
    }
}

__global__ void k_scan(int n) {
    __shared__ int part[1024];
    int t = threadIdx.x;
    int chunk = (n + 1023) / 1024;
    int start = t * chunk;
    int s = 0;
    for (int i = 0; i < chunk; i++) { int j = start + i; if (j < n) s += g_cursor[j]; }
    part[t] = s;
    __syncthreads();
    for (int off = 1; off < 1024; off <<= 1) {
        int v = (t >= off) ? part[t - off] : 0;
        __syncthreads();
        if (t >= off) part[t] += v;
        __syncthreads();
    }
    int run = (t == 0) ? 0 : part[t - 1];
    for (int i = 0; i < chunk; i++) {
        int j = start + i;
        if (j < n) { int c = g_cursor[j]; g_rowptr[j] = run; g_cursor[j] = run; run += c; }
    }
    if (t == 1023) g_rowptr[n] = part[1023];
    if (t == 0) {
        int c = 0;
        for (int k = 0; k < TNN; k++) { g_tcur[k] = c; c += g_tcnt[k]; }
    }
}

__global__ void k_scat(const int* __restrict__ ei, const int* __restrict__ et,
                       const int* __restrict__ nt, int n, int E) {
    int gs = gridDim.x * blockDim.x;
    int gid = blockIdx.x * blockDim.x + threadIdx.x;
    for (int i = gid; i < E; i += gs) {
        int dst = ei[E + i];
        int p = atomicAdd(&g_cursor[dst], 1);
        g_cpack[p] = ei[i] | (et[i] << 24);
    }
    for (int i = gid; i < n; i += gs) {
        int p = atomicAdd(&g_tcur[nt[i]], 1);
        g_order[p] = i;
    }
}

// -------- per-node QKV + QW (R9 version: 256 threads, measured 86.5us) --------
__global__ void __launch_bounds__(256) k_qkv(
    const float* __restrict__ wq, const float* __restrict__ wk,
    const float* __restrict__ wv, const float* __restrict__ wet_l,
    const float* __restrict__ mu_l, const int* __restrict__ ntype,
    int n_nodes) {
    __shared__ float xs [NPB][DD];
    __shared__ float qsh[NPB][DD];
    int t = threadIdx.x;
    if (blockIdx.x == 0 && t < TNN) { g_tcnt[t] = 0; g_tcur[t] = 0; }
    int slot0 = blockIdx.x * NPB;
    int nv = n_nodes - slot0; if (nv > NPB) nv = NPB;

    int nidx[NPB];
    #pragma unroll
    for (int ni = 0; ni < NPB; ni++) {
        int n = g_order[(ni < nv) ? (slot0 + ni) : slot0];
        nidx[ni] = n;
        xs[ni][t] = g_x[n * DD + t];
    }
    int tn0 = ntype[nidx[0]];
    bool uni = true;
    #pragma unroll
    for (int ni = 1; ni < NPB; ni++) uni &= (ntype[nidx[ni]] == tn0);
    __syncthreads();

    int v  = t & 63;
    int h  = v >> 3;
    int c4 = v & 7;

    if (t < 192) {
        int which = t >> 6;
        const float* Wb = (which == 0 ? wq : (which == 1 ? wk : wv));
        int off = h * 32 + c4 * 4;
        int kvoff = (which == 1) ? off : (off + DD);
        if (uni) {
            const float* W = Wb + ((tn0 * HH + h) << 10) + c4 * 4;
            float4 acc[NPB];
            #pragma unroll
            for (int ni = 0; ni < NPB; ni++) acc[ni] = make_float4(0.f, 0.f, 0.f, 0.f);
            #pragma unroll
            for (int d4 = 0; d4 < 8; d4++) {
                float4 w0 = *(const float4*)(W + ((d4 * 4 + 0) << 5));
                float4 w1 = *(const float4*)(W + ((d4 * 4 + 1) << 5));
                float4 w2 = *(const float4*)(W + ((d4 * 4 + 2) << 5));
                float4 w3 = *(const float4*)(W + ((d4 * 4 + 3) << 5));
                #pragma unroll
                for (int ni = 0; ni < NPB; ni++) {
                    float4 xv = *(const float4*)&xs[ni][h * 32 + d4 * 4];
                    acc[ni].x += xv.x*w0.x + xv.y*w1.x + xv.z*w2.x + xv.w*w3.x;
                    acc[ni].y += xv.x*w0.y + xv.y*w1.y + xv.z*w2.y + xv.w*w3.y;
                    acc[ni].z += xv.x*w0.z + xv.y*w1.z + xv.z*w2.z + xv.w*w3.z;
                    acc[ni].w += xv.x*w0.w + xv.y*w1.w + xv.z*w2.w + xv.w*w3.w;
                }
            }
            #pragma unroll
            for (int ni = 0; ni < NPB; ni++) {
                if (which == 0) *(float4*)&qsh[ni][off] = acc[ni];
                else            *(float4*)&g_KV[nidx[ni]*2*DD + kvoff] = acc[ni];
            }
        } else {
            #pragma unroll 1
            for (int ni = 0; ni < NPB; ni++) {
                int tn = ntype[nidx[ni]];
                const float* W = Wb + ((tn * HH + h) << 10) + c4 * 4;
                float4 a = make_float4(0.f, 0.f, 0.f, 0.f);
                #pragma unroll
                for (int d4 = 0; d4 < 8; d4++) {
                    float4 w0 = *(const float4*)(W + ((d4 * 4 + 0) << 5));
                    float4 w1 = *(const float4*)(W + ((d4 * 4 + 1) << 5));
                    float4 w2 = *(const float4*)(W + ((d4 * 4 + 2) << 5));
                    float4 w3 = *(const float4*)(W + ((d4 * 4 + 3) << 5));
                    float4 xv = *(const float4*)&xs[ni][h * 32 + d4 * 4];
                    a.x += xv.x*w0.x + xv.y*w1.x + xv.z*w2.x + xv.w*w3.x;
                    a.y += xv.x*w0.y + xv.y*w1.y + xv.z*w2.y + xv.w*w3.y;
                    a.z += xv.x*w0.z + xv.y*w1.z + xv.z*w2.z + xv.w*w3.z;
                    a.w += xv.x*w0.w + xv.y*w1.w + xv.z*w2.w + xv.w*w3.w;
                }
                if (which == 0) *(float4*)&qsh[ni][off] = a;
                else            *(float4*)&g_KV[nidx[ni]*2*DD + kvoff] = a;
            }
        }
    }
    __syncthreads();

    if (t < 192) {
        int et = t >> 6;
        const float* W = wet_l + ((et * HH + h) << 10) + c4 * 4;
        float c = mu_l[h * TEE + et] * 0.17677669529663687f;
        float4 acc[NPB];
        #pragma unroll
        for (int ni = 0; ni < NPB; ni++) acc[ni] = make_float4(0.f, 0.f, 0.f, 0.f);
        #pragma unroll
        for (int e4 = 0; e4 < 8; e4++) {
            float4 w0 = *(const float4*)(W + ((e4 * 4 + 0) << 5));
            float4 w1 = *(const float4*)(W + ((e4 * 4 + 1) << 5));
            float4 w2 = *(const float4*)(W + ((e4 * 4 + 2) << 5));
            float4 w3 = *(const float4*)(W + ((e4 * 4 + 3) << 5));
            #pragma unroll
            for (int ni = 0; ni < NPB; ni++) {
                float4 xv = *(const float4*)&qsh[ni][h * 32 + e4 * 4];
                acc[ni].x += xv.x*w0.x + xv.y*w1.x + xv.z*w2.x + xv.w*w3.x;
                acc[ni].y += xv.x*w0.y + xv.y*w1.y + xv.z*w2.y + xv.w*w3.y;
                acc[ni].z += xv.x*w0.z + xv.y*w1.z + xv.z*w2.z + xv.w*w3.z;
                acc[ni].w += xv.x*w0.w + xv.y*w1.w + xv.z*w2.w + xv.w*w3.w;
            }
        }
        int off = h * 32 + c4 * 4;
        #pragma unroll
        for (int ni = 0; ni < NPB; ni++) {
            float4 o;
            o.x = acc[ni].x * c; o.y = acc[ni].y * c;
            o.z = acc[ni].z * c; o.w = acc[ni].w * c;
            *(float4*)&g_QW[(nidx[ni] * TEE + et) * DD + off] = o;
        }
    }
}

// -------- edge attention (R9 version: register Q, 4-edge unrolled) ------------
__device__ __forceinline__ float edge_score(int pk, int base,
    const float4& q0a, const float4& q0b, const float4& q1a, const float4& q1b,
    const float4& q2a, const float4& q2b, float4& va, float4& vb) {
    int src = pk & 0xFFFFFF;
    int et  = pk >> 24;
    const float* kp = &g_KV[src * 2 * DD + base];
    float4 ka = *(const float4*)kp, kb = *(const float4*)(kp + 4);
    va = *(const float4*)(kp + DD); vb = *(const float4*)(kp + DD + 4);
    float4 qa = (et == 0) ? q0a : ((et == 1) ? q1a : q2a);
    float4 qb = (et == 0) ? q0b : ((et == 1) ? q1b : q2b);
    float p = ka.x*qa.x + ka.y*qa.y + ka.z*qa.z + ka.w*qa.w
            + kb.x*qb.x + kb.y*qb.y + kb.z*qb.z + kb.w*qb.w;
    p += __shfl_xor_sync(0xffffffffu, p, 1);
    p += __shfl_xor_sync(0xffffffffu, p, 2);
    return p;
}

__global__ void k_attn(int n_nodes) {
    int w = (blockIdx.x * blockDim.x + threadIdx.x) >> 5;
    if (w >= n_nodes) return;
    int l = threadIdx.x & 31;
    if (l == 0) g_cursor[w] = 0;
    int base = ((l >> 2) << 5) + ((l & 3) << 3);

    const float* qwp = &g_QW[(w * 3) * DD + base];
    float4 q0a = *(const float4*)(qwp);
    float4 q0b = *(const float4*)(qwp + 4);
    float4 q1a = *(const float4*)(qwp + DD);
    float4 q1b = *(const float4*)(qwp + DD + 4);
    float4 q2a = *(const float4*)(qwp + 2 * DD);
    float4 q2b = *(const float4*)(qwp + 2 * DD + 4);

    float m = -1e30f, s = 0.f;
    float a0=0,a1=0,a2=0,a3=0,a4=0,a5=0,a6=0,a7=0;
    int r0 = g_rowptr[w], r1 = g_rowptr[w + 1];
    int i = r0;
    for (; i + 4 <= r1; i += 4) {
        int pk0 = g_cpack[i],   pk1 = g_cpack[i+1];
        int pk2 = g_cpack[i+2], pk3 = g_cpack[i+3];
        float4 v0a, v0b, v1a, v1b, v2a, v2b, v3a, v3b;
        float p0 = edge_score(pk0, base, q0a,q0b,q1a,q1b,q2a,q2b, v0a, v0b);
        float p1 = edge_score(pk1, base, q0a,q0b,q1a,q1b,q2a,q2b, v1a, v1b);
        float p2 = edge_score(pk2, base, q0a,q0b,q1a,q1b,q2a,q2b, v2a, v2b);
        float p3 = edge_score(pk3, base, q0a,q0b,q1a,q1b,q2a,q2b, v3a, v3b);
        float mn = fmaxf(fmaxf(m, fmaxf(p0, p1)), fmaxf(p2, p3));
        float f  = __expf(m - mn);
        float e0 = __expf(p0 - mn);
        float e1 = __expf(p1 - mn);
        float e2 = __expf(p2 - mn);
        float e3 = __expf(p3 - mn);
        m = mn;
        s = s * f + (e0 + e1) + (e2 + e3);
        a0 = a0*f + e0*v0a.x + e1*v1a.x + e2*v2a.x + e3*v3a.x;
        a1 = a1*f + e0*v0a.y + e1*v1a.y + e2*v2a.y + e3*v3a.y;
        a2 = a2*f + e0*v0a.z + e1*v1a.z + e2*v2a.z + e3*v3a.z;
        a3 = a3*f + e0*v0a.w + e1*v1a.w + e2*v2a.w + e3*v3a.w;
        a4 = a4*f + e0*v0b.x + e1*v1b.x + e2*v2b.x + e3*v3b.x;
        a5 = a5*f + e0*v0b.y + e1*v1b.y + e2*v2b.y + e3*v3b.y;
        a6 = a6*f + e0*v0b.z + e1*v1b.z + e2*v2b.z + e3*v3b.z;
        a7 = a7*f + e0*v0b.w + e1*v1b.w + e2*v2b.w + e3*v3b.w;
    }
    for (; i < r1; i++) {
        float4 va, vb;
        float p = edge_score(g_cpack[i], base, q0a,q0b,q1a,q1b,q2a,q2b, va, vb);
        float mn = fmaxf(m, p);
        float f  = __expf(m - mn);
        float e  = __expf(p - mn);
        m = mn;
        s = s * f + e;
        a0 = a0*f + e*va.x; a1 = a1*f + e*va.y; a2 = a2*f + e*va.z; a3 = a3*f + e*va.w;
        a4 = a4*f + e*vb.x; a5 = a5*f + e*vb.y; a6 = a6*f + e*vb.z; a7 = a7*f + e*vb.w;
    }
    float inv = 1.0f / (s + 1e-10f);
    float o[8] = { a0*inv, a1*inv, a2*inv, a3*inv, a4*inv, a5*inv, a6*inv, a7*inv };
    __nv_bfloat16 h[8], lo[8];
    #pragma unroll
    for (int q = 0; q < 8; q++) split_bf16(o[q], h[q], lo[q]);
    *(uint4*)&g_aggH[w * DD + base] = *(uint4*)h;
    *(uint4*)&g_aggL[w * DD + base] = *(uint4*)lo;
}

// ============== pipelined tensor-core GEMM (bf16x3, cp.async) ================
// generic kernel: used for w1 (N=1024, GELU -> bf16 hi/lo out)
#define PADB  80
#define TILEB 10240
#define SM_AH 0
#define SM_AL (TILEB)
#define SM_BH (2*TILEB)
#define SM_BL (3*TILEB)
#define STAGEB (4*TILEB)
#define GEMM_SMEM (2*STAGEB)

__device__ __forceinline__ void gemm_load_stage(
    uint32_t smb, int stage,
    const __nv_bfloat16* __restrict__ Ahi, const __nv_bfloat16* __restrict__ Alo,
    const __nv_bfloat16* __restrict__ Bhi, const __nv_bfloat16* __restrict__ Blo,
    int row0, int col0, int k0, int M, int K, int tid)
{
    uint32_t sp = smb + stage * STAGEB;
    #pragma unroll
    for (int it = 0; it < 2; it++) {
        int idx = tid + it * 256;
        int row = idx >> 2, seg = idx & 3;
        uint32_t off = row * PADB + seg * 16;
        size_t goff = (size_t)(row0 + row) * K + k0 + seg * 8;
        bool v = (row0 + row) < M;
        cp16z(sp + SM_AH + off, Ahi + goff, v);
        cp16z(sp + SM_AL + off, Alo + goff, v);
    }
    #pragma unroll
    for (int it = 0; it < 2; it++) {
        int idx = tid + it * 256;
        int n = idx >> 2, seg = idx & 3;
        uint32_t off = n * PADB + seg * 16;
        size_t goff = (size_t)(col0 + n) * K + k0 + seg * 8;
        cp16z(sp + SM_BH + off, Bhi + goff, true);
        cp16z(sp + SM_BL + off, Blo + goff, true);
    }
}

__global__ void __launch_bounds__(256, 2) k_gemm_mma(
    const __nv_bfloat16* __restrict__ Ahi, const __nv_bfloat16* __restrict__ Alo,
    const __nv_bfloat16* __restrict__ Bhi, const __nv_bfloat16* __restrict__ Blo,
    const float* __restrict__ bias,
    __nv_bfloat16* __restrict__ Chi, __nv_bfloat16* __restrict__ Clo,
    int M, int N, int K)
{
    extern __shared__ __align__(16) char smem[];
    uint32_t smb = smem_to_u32(smem);
    int tid = threadIdx.x, wid = tid >> 5, lane = tid & 31;
    int row0 = blockIdx.y * 128, col0 = blockIdx.x * 128;
    int wm = wid & 3, wn = wid >> 2;

    float acc[2][8][4];
    #pragma unroll
    for (int a = 0; a < 2; a++)
        #pragma unroll
        for (int b = 0; b < 8; b++)
            #pragma unroll
            for (int c = 0; c < 4; c++) acc[a][b][c] = 0.f;

    uint32_t a_row  = wm * 32 + (lane & 15);
    uint32_t a_col8 = (lane >> 4) * 8;
    uint32_t b_row  = wn * 64 + ((lane >> 4) & 1) * 8 + (lane & 7);
    uint32_t b_col8 = ((lane >> 3) & 1) * 8;

    int nc = K >> 5;
    gemm_load_stage(smb, 0, Ahi, Alo, Bhi, Blo, row0, col0, 0, M, K, tid);
    CP_COMMIT();

    for (int c = 0; c < nc; c++) {
        if (c + 1 < nc) {
            gemm_load_stage(smb, (c + 1) & 1, Ahi, Alo, Bhi, Blo,
                            row0, col0, (c + 1) << 5, M, K, tid);
            CP_COMMIT();
            CP_WAIT1();
        } else {
            CP_WAIT0();
        }
        __syncthreads();
        uint32_t sp = smb + (c & 1) * STAGEB;
        #pragma unroll
        for (int kk = 0; kk < 2; kk++) {
            uint32_t ah[2][4], al[2][4];
            #pragma unroll
            for (int mt = 0; mt < 2; mt++) {
                uint32_t off = (a_row + mt * 16) * PADB + (kk * 16 + a_col8) * 2;
                ldmat_x4(ah[mt], sp + SM_AH + off);
                ldmat_x4(al[mt], sp + SM_AL + off);
            }
            #pragma unroll
            for (int p = 0; p < 4; p++) {
                uint32_t bh[4], bl[4];
                uint32_t off = (b_row + p * 16) * PADB + (kk * 16 + b_col8) * 2;
                ldmat_x4(bh, sp + SM_BH + off);
                ldmat_x4(bl, sp + SM_BL + off);
                #pragma unroll
                for (int mt = 0; mt < 2; mt++) {
                    mma_bf16(acc[mt][p * 2 + 0], ah[mt], &bh[0]);
                    mma_bf16(acc[mt][p * 2 + 1], ah[mt], &bh[2]);
                    mma_bf16(acc[mt][p * 2 + 0], ah[mt], &bl[0]);
                    mma_bf16(acc[mt][p * 2 + 1], ah[mt], &bl[2]);
                    mma_bf16(acc[mt][p * 2 + 0], al[mt], &bh[0]);
                    mma_bf16(acc[mt][p * 2 + 1], al[mt], &bh[2]);
                }
            }
        }
        __syncthreads();
    }

    int g = lane >> 2, tg = lane & 3;
    #pragma unroll
    for (int mt = 0; mt < 2; mt++) {
        int r_hi = row0 + wm * 32 + mt * 16 + g;
        #pragma unroll
        for (int j = 0; j < 8; j++) {
            int cc = col0 + wn * 64 + j * 8 + tg * 2;
            float bx = bias[cc], by = bias[cc + 1];
            #pragma unroll
            for (int half = 0; half < 2; half++) {
                int r = r_hi + half * 8;
                if (r >= M) continue;
                float ox = gelu_f(acc[mt][j][half * 2 + 0] + bx);
                float oy = gelu_f(acc[mt][j][half * 2 + 1] + by);
                __nv_bfloat16 hx, lx, hy, ly;
                split_bf16(ox, hx, lx);
                split_bf16(oy, hy, ly);
                __nv_bfloat162 hv; hv.x = hx; hv.y = hy;
                __nv_bfloat162 lv; lv.x = lx; lv.y = ly;
                *(__nv_bfloat162*)&Chi[(size_t)r * N + cc] = hv;
                *(__nv_bfloat162*)&Clo[(size_t)r * N + cc] = lv;
            }
        }
    }
}

// ===== fused GEMM (N=256) + bias + residual + LayerNorm =======================
// CTA tile 128x256, 512 threads (16 warps: 4M x 4N), K-chunk 32, 2-stage.
#define LPADB  80
#define LA_H   0
#define LA_L   10240
#define LB_H   20480
#define LB_L   40960
#define LSTAGE 61440
#define LNG_SMEM (2*LSTAGE)

__device__ __forceinline__ void gemmln_load_stage(
    uint32_t smb, int stage,
    const __nv_bfloat16* __restrict__ Ahi, const __nv_bfloat16* __restrict__ Alo,
    const __nv_bfloat16* __restrict__ Bhi, const __nv_bfloat16* __restrict__ Blo,
    int row0, int k0, int M, int K, int tid)
{
    uint32_t sp = smb + stage * LSTAGE;
    {   // A: 128 rows x 32 bf16 (hi & lo)
        int row = tid >> 2, seg = tid & 3;
        uint32_t off = row * LPADB + seg * 16;
        size_t goff = (size_t)(row0 + row) * K + k0 + seg * 8;
        bool v = (row0 + row) < M;
        cp16z(sp + LA_H + off, Ahi + goff, v);
        cp16z(sp + LA_L + off, Alo + goff, v);
    }
    #pragma unroll
    for (int it = 0; it < 2; it++) {   // B: 256 rows x 32 bf16 (hi & lo)
        int idx = tid + it * 512;
        int n = idx >> 2, seg = idx & 3;
        uint32_t off = n * LPADB + seg * 16;
        size_t goff = (size_t)n * K + k0 + seg * 8;
        cp16z(sp + LB_H + off, Bhi + goff, true);
        cp16z(sp + LB_L + off, Blo + goff, true);
    }
}

__global__ void __launch_bounds__(512, 1) k_gemm_ln(
    const __nv_bfloat16* __restrict__ Ahi, const __nv_bfloat16* __restrict__ Alo,
    const __nv_bfloat16* __restrict__ Bhi, const __nv_bfloat16* __restrict__ Blo,
    const float* __restrict__ bias, const float* __restrict__ xin,
    const float* __restrict__ lng, const float* __restrict__ lnb,
    float* __restrict__ xout,
    __nv_bfloat16* __restrict__ outH, __nv_bfloat16* __restrict__ outL,
    int M, int K)
{
    extern __shared__ __align__(16) char smem[];
    uint32_t smb = smem_to_u32(smem);
    int tid = threadIdx.x, wid = tid >> 5, lane = tid & 31;
    int row0 = blockIdx.x * 128;
    int wm = wid & 3, wn = wid >> 2;   // wn in 0..3 (4 x 64 cols = 256)

    float acc[2][8][4];
    #pragma unroll
    for (int a = 0; a < 2; a++)
        #pragma unroll
        for (int b = 0; b < 8; b++)
            #pragma unroll
            for (int c = 0; c < 4; c++) acc[a][b][c] = 0.f;

    uint32_t a_row  = wm * 32 + (lane & 15);
    uint32_t a_col8 = (lane >> 4) * 8;
    uint32_t b_row  = wn * 64 + ((lane >> 4) & 1) * 8 + (lane & 7);
    uint32_t b_col8 = ((lane >> 3) & 1) * 8;

    int nc = K >> 5;
    gemmln_load_stage(smb, 0, Ahi, Alo, Bhi, Blo, row0, 0, M, K, tid);
    CP_COMMIT();

    for (int c = 0; c < nc; c++) {
        if (c + 1 < nc) {
            gemmln_load_stage(smb, (c + 1) & 1, Ahi, Alo, Bhi, Blo,
                              row0, (c + 1) << 5, M, K, tid);
            CP_COMMIT();
            CP_WAIT1();
        } else {
            CP_WAIT0();
        }
        __syncthreads();
        uint32_t sp = smb + (c & 1) * LSTAGE;
        #pragma unroll
        for (int kk = 0; kk < 2; kk++) {
            uint32_t ah[2][4], al[2][4];
            #pragma unroll
            for (int mt = 0; mt < 2; mt++) {
                uint32_t off = (a_row + mt * 16) * LPADB + (kk * 16 + a_col8) * 2;
                ldmat_x4(ah[mt], sp + LA_H + off);
                ldmat_x4(al[mt], sp + LA_L + off);
            }
            #pragma unroll
            for (int p = 0; p < 4; p++) {
                uint32_t bh[4], bl[4];
                uint32_t off = (b_row + p * 16) * LPADB + (kk * 16 + b_col8) * 2;
                ldmat_x4(bh, sp + LB_H + off);
                ldmat_x4(bl, sp + LB_L + off);
                #pragma unroll
                for (int mt = 0; mt < 2; mt++) {
                    mma_bf16(acc[mt][p * 2 + 0], ah[mt], &bh[0]);
                    mma_bf16(acc[mt][p * 2 + 1], ah[mt], &bh[2]);
                    mma_bf16(acc[mt][p * 2 + 0], ah[mt], &bl[0]);
                    mma_bf16(acc[mt][p * 2 + 1], ah[mt], &bl[2]);
                    mma_bf16(acc[mt][p * 2 + 0], al[mt], &bh[0]);
                    mma_bf16(acc[mt][p * 2 + 1], al[mt], &bh[2]);
                }
            }
        }
        __syncthreads();
    }

    // ---- fused epilogue: val = acc + bias + residual, then LayerNorm --------
    int g = lane >> 2, tg = lane & 3;
    float psum[2][2] = {{0.f, 0.f}, {0.f, 0.f}};
    float psq [2][2] = {{0.f, 0.f}, {0.f, 0.f}};
    #pragma unroll
    for (int mt = 0; mt < 2; mt++) {
        #pragma unroll
        for (int half = 0; half < 2; half++) {
            int r = row0 + wm * 32 + mt * 16 + g + half * 8;
            if (r >= M) continue;
            #pragma unroll
            for (int j = 0; j < 8; j++) {
                int cc = wn * 64 + j * 8 + tg * 2;
                float2 xv = *(const float2*)&xin[(size_t)r * DD + cc];
                float v0 = acc[mt][j][half * 2 + 0] + bias[cc]     + xv.x;
                float v1 = acc[mt][j][half * 2 + 1] + bias[cc + 1] + xv.y;
                acc[mt][j][half * 2 + 0] = v0;
                acc[mt][j][half * 2 + 1] = v1;
                psum[mt][half] += v0 + v1;
                psq [mt][half] += v0 * v0 + v1 * v1;
            }
        }
    }
    // reduce across the 4 tg lanes (consecutive lanes within the g-quad)
    #pragma unroll
    for (int mt = 0; mt < 2; mt++)
        #pragma unroll
        for (int half = 0; half < 2; half++) {
            psum[mt][half] += __shfl_xor_sync(0xffffffffu, psum[mt][half], 1);
            psum[mt][half] += __shfl_xor_sync(0xffffffffu, psum[mt][half], 2);
            psq [mt][half] += __shfl_xor_sync(0xffffffffu, psq [mt][half], 1);
            psq [mt][half] += __shfl_xor_sync(0xffffffffu, psq [mt][half], 2);
        }
    // cross-warp (wn) reduction via smem (tiles are dead now)
    float* redS = (float*)smem;          // [128][4]
    float* redQ = (float*)smem + 512;    // [128][4]
    if (tg == 0) {
        #pragma unroll
        for (int mt = 0; mt < 2; mt++)
            #pragma unroll
            for (int half = 0; half < 2; half++) {
                int rl = wm * 32 + mt * 16 + g + half * 8;
                redS[rl * 4 + wn] = psum[mt][half];
                redQ[rl * 4 + wn] = psq [mt][half];
            }
    }
    __syncthreads();
    #pragma unroll
    for (int mt = 0; mt < 2; mt++) {
        #pragma unroll
        for (int half = 0; half < 2; half++) {
            int rl = wm * 32 + mt * 16 + g + half * 8;
            int r = row0 + rl;
            if (r >= M) continue;
            float s = redS[rl*4+0] + redS[rl*4+1] + redS[rl*4+2] + redS[rl*4+3];
            float q = redQ[rl*4+0] + redQ[rl*4+1] + redQ[rl*4+2] + redQ[rl*4+3];
            float mean = s * (1.0f / 256.0f);
            float var  = q * (1.0f / 256.0f) - mean * mean;
            float inv  = rsqrtf(var + 1e-5f);
            #pragma unroll
            for (int j = 0; j < 8; j++) {
                int cc = wn * 64 + j * 8 + tg * 2;
                float o0 = (acc[mt][j][half*2+0] - mean) * inv * lng[cc]     + lnb[cc];
                float o1 = (acc[mt][j][half*2+1] - mean) * inv * lng[cc + 1] + lnb[cc + 1];
                float2 ov; ov.x = o0; ov.y = o1;
                *(float2*)&xout[(size_t)r * DD + cc] = ov;
                if (outH) {
                    __nv_bfloat16 h0, l0, h1, l1;
                    split_bf16(o0, h0, l0);
                    split_bf16(o1, h1, l1);
                    __nv_bfloat162 hv; hv.x = h0; hv.y = h1;
                    __nv_bfloat162 lv; lv.x = l0; lv.y = l1;
                    *(__nv_bfloat162*)&outH[(size_t)r * DD + cc] = hv;
                    *(__nv_bfloat162*)&outL[(size_t)r * DD + cc] = lv;
                }
            }
        }
    }
}

// -------- final LayerNorm: warp per node ---------------------------------------
__global__ void k_lnres(const float* __restrict__ xin,
                        const float* __restrict__ g, const float* __restrict__ b,
                        float* __restrict__ xout, int n_nodes) {
    int w = (blockIdx.x * blockDim.x + threadIdx.x) >> 5;
    if (w >= n_nodes) return;
    int lane = threadIdx.x & 31;
    int off = w * DD + lane * 8;

    float4 va = *(const float4*)&xin[off];
    float4 vb = *(const float4*)&xin[off + 4];
    float sum = va.x + va.y + va.z + va.w + vb.x + vb.y + vb.z + vb.w;
    #pragma unroll
    for (int o = 16; o; o >>= 1) sum += __shfl_xor_sync(0xffffffffu, sum, o);
    float mean = sum * (1.0f / 256.0f);
    float d[8] = { va.x-mean, va.y-mean, va.z-mean, va.w-mean,
                   vb.x-mean, vb.y-mean, vb.z-mean, vb.w-mean };
    float vs = 0.f;
    #pragma unroll
    for (int q = 0; q < 8; q++) vs += d[q] * d[q];
    #pragma unroll
    for (int o = 16; o; o >>= 1) vs += __shfl_xor_sync(0xffffffffu, vs, o);
    float inv = rsqrtf(vs * (1.0f / 256.0f) + 1e-5f);

    float4 ga = *(const float4*)&g[lane * 8];
    float4 gb = *(const float4*)&g[lane * 8 + 4];
    float4 ba = *(const float4*)&b[lane * 8];
    float4 bb = *(const float4*)&b[lane * 8 + 4];
    float r[8];
    r[0] = d[0]*inv*ga.x + ba.x; r[1] = d[1]*inv*ga.y + ba.y;
    r[2] = d[2]*inv*ga.z + ba.z; r[3] = d[3]*inv*ga.w + ba.w;
    r[4] = d[4]*inv*gb.x + bb.x; r[5] = d[5]*inv*gb.y + bb.y;
    r[6] = d[6]*inv*gb.z + bb.z; r[7] = d[7]*inv*gb.w + bb.w;
    *(float4*)&xout[off]     = make_float4(r[0], r[1], r[2], r[3]);
    *(float4*)&xout[off + 4] = make_float4(r[4], r[5], r[6], r[7]);
}

// ---------------- host ---------------------------------------------------------
extern "C" void kernel_launch(void* const* d_in, const int* in_sizes, int n_in,
                              void* d_out, int out_size) {
    const float* x     = (const float*)d_in[0];
    const int*   ei    = (const int*)  d_in[1];
    const int*   etype = (const int*)  d_in[2];
    const int*   ntype = (const int*)  d_in[3];
    const float* WQ    = (const float*)d_in[4];
    const float* WK    = (const float*)d_in[5];
    const float* WV    = (const float*)d_in[6];
    const float* WE    = (const float*)d_in[7];
    const float* mu    = (const float*)d_in[8];
    const float* Wo    = (const float*)d_in[9];
    const float* bo    = (const float*)d_in[10];
    const float* ln1g  = (const float*)d_in[11];
    const float* ln1b  = (const float*)d_in[12];
    const float* ln2g  = (const float*)d_in[13];
    const float* ln2b  = (const float*)d_in[14];
    const float* w1    = (const float*)d_in[15];
    const float* b1    = (const float*)d_in[16];
    const float* w2    = (const float*)d_in[17];
    const float* b2    = (const float*)d_in[18];
    const float* outg  = (const float*)d_in[19];
    const float* outb  = (const float*)d_in[20];

    int N = in_sizes[0] / DD;
    int E = in_sizes[2];

    float *px, *pwet;
    cudaGetSymbolAddress((void**)&px,   g_x);
    cudaGetSymbolAddress((void**)&pwet, g_WET);

    __nv_bfloat16 *pAggH, *pAggL, *pXH, *pXL, *pFH, *pFL;
    cudaGetSymbolAddress((void**)&pAggH, g_aggH);
    cudaGetSymbolAddress((void**)&pAggL, g_aggL);
    cudaGetSymbolAddress((void**)&pXH,   g_xH);
    cudaGetSymbolAddress((void**)&pXL,   g_xL);
    cudaGetSymbolAddress((void**)&pFH,   g_ffnH);
    cudaGetSymbolAddress((void**)&pFL,   g_ffnL);

    __nv_bfloat16 *pWoH, *pWoL, *pW1H, *pW1L, *pW2H, *pW2L;
    cudaGetSymbolAddress((void**)&pWoH, g_WoT_hi);
    cudaGetSymbolAddress((void**)&pWoL, g_WoT_lo);
    cudaGetSymbolAddress((void**)&pW1H, g_W1T_hi);
    cudaGetSymbolAddress((void**)&pW1L, g_W1T_lo);
    cudaGetSymbolAddress((void**)&pW2H, g_W2T_hi);
    cudaGetSymbolAddress((void**)&pW2L, g_W2T_lo);

    cudaFuncSetAttribute(k_gemm_mma, cudaFuncAttributeMaxDynamicSharedMemorySize, GEMM_SMEM);
    cudaFuncSetAttribute(k_gemm_ln,  cudaFuncAttributeMaxDynamicSharedMemorySize, LNG_SMEM);

    cudaMemcpyAsync(px, x, (size_t)N * DD * sizeof(float), cudaMemcpyDeviceToDevice, 0);

    // preprocessing (3 launches)
    k_count<<<1250, 256>>>(ei, ntype, WE, Wo, w1, w2, N, E);
    k_scan<<<1, 1024>>>(N);
    k_scat<<<(E + 255) / 256, 256>>>(ei, etype, ntype, N, E);

    int mtiles = (N + 127) / 128;
    int lnblocks = (N + 7) / 8;

    for (int l = 0; l < LLAY; l++) {
        const float* wq  = WQ + (size_t)l * TNN * HH * 1024;
        const float* wk  = WK + (size_t)l * TNN * HH * 1024;
        const float* wv  = WV + (size_t)l * TNN * HH * 1024;
        const float* mul = mu + (size_t)l * HH * TEE;
        const float* bol = bo + (size_t)l * DD;
        const float* b1l = b1 + (size_t)l * FF;
        const float* b2l = b2 + (size_t)l * DD;
        const float* wetl = pwet + (size_t)l * TEE * HH * 1024;

        k_qkv<<<(N + NPB - 1) / NPB, 256>>>(wq, wk, wv, wetl, mul, ntype, N);
        k_attn<<<(N * 32 + 255) / 256, 256>>>(N);

        // fused: y = agg@Wo + bo;  x = LN(x + y); also emit xH/xL for w1
        k_gemm_ln<<<mtiles, 512, LNG_SMEM>>>(pAggH, pAggL,
            pWoH + (size_t)l * DD * DD, pWoL + (size_t)l * DD * DD,
            bol, px, ln1g + l * DD, ln1b + l * DD, px, pXH, pXL, N, DD);

        // w1: x @ w1 + b1 -> GELU -> ffn bf16 hi/lo
        {
            dim3 grid(FF / 128, mtiles);
            k_gemm_mma<<<grid, 256, GEMM_SMEM>>>(pXH, pXL,
                pW1H + (size_t)l * FF * DD, pW1L + (size_t)l * FF * DD,
                b1l, pFH, pFL, N, FF, DD);
        }
        // fused: y = ffn@w2 + b2;  x = LN(x + y)
        k_gemm_ln<<<mtiles, 512, LNG_SMEM>>>(pFH, pFL,
            pW2H + (size_t)l * DD * FF, pW2L + (size_t)l * DD * FF,
            b2l, px, ln2g + l * DD, ln2b + l * DD, px,
            (__nv_bfloat16*)nullptr, (__nv_bfloat16*)nullptr, N, FF);
    }

    k_lnres<<<lnblocks, 256>>>(px, outg, outb, (float*)d_out, N);
}

// round 14
// speedup vs baseline: 1.1458x; 1.1458x over previous
#include <cuda_runtime.h>
#include <cuda_bf16.h>
#include <math.h>
#include <stdint.h>

#define NMAX 20000
#define EMAX 320000
#define DD   256
#define HH   8
#define HDD  32
#define TEE  3
#define TNN  4
#define LLAY 3
#define FF   1024
#define NPB  8

// ---------------- scratch (device globals; zero-initialized at load) --------
__device__ float g_x   [NMAX*DD];
__device__ float g_KV  [NMAX*2*DD];
__device__ float g_QW  [NMAX*TEE*DD];
__device__ float g_y   [NMAX*DD];
__device__ int   g_rowptr[NMAX+1];
__device__ int   g_cursor[NMAX];      // zero at entry (re-zeroed by k_attn)
__device__ int   g_cpack [EMAX];
__device__ int   g_order [NMAX];
__device__ int   g_tcnt  [TNN];       // zero at entry (re-zeroed by k_qkv)
__device__ int   g_tcur  [TNN];
__device__ float g_WET [LLAY*TEE*HH*HDD*HDD];

__device__ __nv_bfloat16 g_aggH[NMAX*DD];
__device__ __nv_bfloat16 g_aggL[NMAX*DD];
__device__ __nv_bfloat16 g_xH  [NMAX*DD];
__device__ __nv_bfloat16 g_xL  [NMAX*DD];
__device__ __nv_bfloat16 g_ffnH[NMAX*FF];
__device__ __nv_bfloat16 g_ffnL[NMAX*FF];

__device__ __nv_bfloat16 g_WoT_hi[LLAY*DD*DD];
__device__ __nv_bfloat16 g_WoT_lo[LLAY*DD*DD];
__device__ __nv_bfloat16 g_W1T_hi[LLAY*FF*DD];
__device__ __nv_bfloat16 g_W1T_lo[LLAY*FF*DD];
__device__ __nv_bfloat16 g_W2T_hi[LLAY*DD*FF];
__device__ __nv_bfloat16 g_W2T_lo[LLAY*DD*FF];

// ---------------- helpers ------------------------------------------------
__device__ __forceinline__ float gelu_f(float v) {
    return 0.5f * v * (1.0f + erff(v * 0.70710678118654752f));
}
__device__ __forceinline__ uint32_t smem_to_u32(const void* p) {
    uint32_t a;
    asm("{ .reg .u64 t; cvta.to.shared.u64 t, %1; cvt.u32.u64 %0, t; }" : "=r"(a) : "l"(p));
    return a;
}
__device__ __forceinline__ void ldmat_x4(uint32_t* r, uint32_t addr) {
    asm volatile("ldmatrix.sync.aligned.m8n8.x4.shared.b16 {%0,%1,%2,%3}, [%4];"
        : "=r"(r[0]), "=r"(r[1]), "=r"(r[2]), "=r"(r[3]) : "r"(addr));
}
__device__ __forceinline__ void mma_bf16(float* d, const uint32_t* a, const uint32_t* b) {
    asm volatile("mma.sync.aligned.m16n8k16.row.col.f32.bf16.bf16.f32 "
        "{%0,%1,%2,%3}, {%4,%5,%6,%7}, {%8,%9}, {%0,%1,%2,%3};"
        : "+f"(d[0]), "+f"(d[1]), "+f"(d[2]), "+f"(d[3])
        : "r"(a[0]), "r"(a[1]), "r"(a[2]), "r"(a[3]), "r"(b[0]), "r"(b[1]));
}
__device__ __forceinline__ void cp16z(uint32_t dst, const void* src, bool valid) {
    int sz = valid ? 16 : 0;
    asm volatile("cp.async.cg.shared.global [%0], [%1], 16, %2;"
        :: "r"(dst), "l"(src), "r"(sz));
}
#define CP_COMMIT()  asm volatile("cp.async.commit_group;" ::: "memory")
#define CP_WAIT1()   asm volatile("cp.async.wait_group 1;" ::: "memory")
#define CP_WAIT0()   asm volatile("cp.async.wait_group 0;" ::: "memory")

__device__ __forceinline__ void split_bf16(float v, __nv_bfloat16& h, __nv_bfloat16& l) {
    h = __float2bfloat16_rn(v);
    l = __float2bfloat16_rn(v - __bfloat162float(h));
}

// ======= preprocessing (3 launches) ===========================================
__device__ __forceinline__ void splitT_one(const float* W, __nv_bfloat16* hi,
                                           __nv_bfloat16* lo, int K, int N, int i) {
    int k = i / N, n = i % N;
    float w = W[i];
    __nv_bfloat16 h, l; split_bf16(w, h, l);
    hi[(size_t)n * K + k] = h;
    lo[(size_t)n * K + k] = l;
}

// launch #1: x copy + edge/node counting + all weight prep
__global__ void k_count(const float* __restrict__ x,
                        const int* __restrict__ ei, const int* __restrict__ nt,
                        const float* __restrict__ WE, const float* __restrict__ Wo,
                        const float* __restrict__ w1, const float* __restrict__ w2,
                        int n, int E) {
    int gs = gridDim.x * blockDim.x;
    int gid = blockIdx.x * blockDim.x + threadIdx.x;
    for (int i = gid; i < n * DD / 4; i += gs)
        ((float4*)g_x)[i] = ((const float4*)x)[i];
    for (int i = gid; i < E; i += gs) atomicAdd(&g_cursor[ei[E + i]], 1);
    for (int i = gid; i < n; i += gs) atomicAdd(&g_tcnt[nt[i]], 1);
    for (int i = gid; i < LLAY * TEE * HH * HDD * HDD; i += gs) {
        int d = i & 31, e = (i >> 5) & 31, base = i >> 10;
        g_WET[i] = WE[(base << 10) + (d << 5) + e];
    }
    for (int i = gid; i < LLAY * DD * DD; i += gs) {
        int l = i / (DD * DD), j = i % (DD * DD);
        splitT_one(Wo + (size_t)l * DD * DD, g_WoT_hi + (size_t)l * DD * DD,
                   g_WoT_lo + (size_t)l * DD * DD, DD, DD, j);
    }
    for (int i = gid; i < LLAY * DD * FF; i += gs) {
        int l = i / (DD * FF), j = i % (DD * FF);
        splitT_one(w1 + (size_t)l * DD * FF, g_W1T_hi + (size_t)l * FF * DD,
                   g_W1T_lo + (size_t)l * FF * DD, DD, FF, j);
    }
    for (int i = gid; i < LLAY * FF * DD; i += gs) {
        int l = i / (FF * DD), j = i % (FF * DD);
        splitT_one(w2 + (size_t)l * FF * DD, g_W2T_hi + (size_t)l * DD * FF,
                   g_W2T_lo + (size_t)l * DD * FF, FF, DD, j);
    }
}

// launch #2: shfl-based two-level scan (2 barriers)
__global__ void k_scan(int n) {
    __shared__ int wsum[32];
    int t = threadIdx.x;
    int lane = t & 31, wid = t >> 5;
    int chunk = (n + 1023) / 1024;
    int start = t * chunk;
    int end = start + chunk; if (end > n) end = n;

    int s = 0;
    for (int j = start; j < end; j++) s += g_cursor[j];
    // inclusive warp scan
    int ps = s;
    #pragma unroll
    for (int o = 1; o < 32; o <<= 1) {
        int v = __shfl_up_sync(0xffffffffu, ps, o);
        if (lane >= o) ps += v;
    }
    if (lane == 31) wsum[wid] = ps;
    __syncthreads();
    if (wid == 0) {
        int v = wsum[lane];
        int pv = v;
        #pragma unroll
        for (int o = 1; o < 32; o <<= 1) {
            int u = __shfl_up_sync(0xffffffffu, pv, o);
            if (lane >= o) pv += u;
        }
        wsum[lane] = pv;
    }
    __syncthreads();
    int base = ps - s + ((wid > 0) ? wsum[wid - 1] : 0);   // exclusive prefix
    int run = base;
    for (int j = start; j < end; j++) {
        int c = g_cursor[j];
        g_rowptr[j] = run;
        g_cursor[j] = run;
        run += c;
    }
    if (t == 0) {
        g_rowptr[n] = wsum[31];
        int c = 0;
        for (int k = 0; k < TNN; k++) { g_tcur[k] = c; c += g_tcnt[k]; }
    }
}

// launch #3
__global__ void k_scat(const int* __restrict__ ei, const int* __restrict__ et,
                       const int* __restrict__ nt, int n, int E) {
    int gs = gridDim.x * blockDim.x;
    int gid = blockIdx.x * blockDim.x + threadIdx.x;
    for (int i = gid; i < E; i += gs) {
        int dst = ei[E + i];
        int p = atomicAdd(&g_cursor[dst], 1);
        g_cpack[p] = ei[i] | (et[i] << 24);
    }
    for (int i = gid; i < n; i += gs) {
        int p = atomicAdd(&g_tcur[nt[i]], 1);
        g_order[p] = i;
    }
}

// -------- per-node QKV + QW (R9 version, measured 86.5us/layer) ---------------
__global__ void __launch_bounds__(256) k_qkv(
    const float* __restrict__ wq, const float* __restrict__ wk,
    const float* __restrict__ wv, const float* __restrict__ wet_l,
    const float* __restrict__ mu_l, const int* __restrict__ ntype,
    int n_nodes) {
    __shared__ float xs [NPB][DD];
    __shared__ float qsh[NPB][DD];
    int t = threadIdx.x;
    if (blockIdx.x == 0 && t < TNN) { g_tcnt[t] = 0; g_tcur[t] = 0; }
    int slot0 = blockIdx.x * NPB;
    int nv = n_nodes - slot0; if (nv > NPB) nv = NPB;

    int nidx[NPB];
    #pragma unroll
    for (int ni = 0; ni < NPB; ni++) {
        int n = g_order[(ni < nv) ? (slot0 + ni) : slot0];
        nidx[ni] = n;
        xs[ni][t] = g_x[n * DD + t];
    }
    int tn0 = ntype[nidx[0]];
    bool uni = true;
    #pragma unroll
    for (int ni = 1; ni < NPB; ni++) uni &= (ntype[nidx[ni]] == tn0);
    __syncthreads();

    int v  = t & 63;
    int h  = v >> 3;
    int c4 = v & 7;

    if (t < 192) {
        int which = t >> 6;
        const float* Wb = (which == 0 ? wq : (which == 1 ? wk : wv));
        int off = h * 32 + c4 * 4;
        int kvoff = (which == 1) ? off : (off + DD);
        if (uni) {
            const float* W = Wb + ((tn0 * HH + h) << 10) + c4 * 4;
            float4 acc[NPB];
            #pragma unroll
            for (int ni = 0; ni < NPB; ni++) acc[ni] = make_float4(0.f, 0.f, 0.f, 0.f);
            #pragma unroll
            for (int d4 = 0; d4 < 8; d4++) {
                float4 w0 = *(const float4*)(W + ((d4 * 4 + 0) << 5));
                float4 w1 = *(const float4*)(W + ((d4 * 4 + 1) << 5));
                float4 w2 = *(const float4*)(W + ((d4 * 4 + 2) << 5));
                float4 w3 = *(const float4*)(W + ((d4 * 4 + 3) << 5));
                #pragma unroll
                for (int ni = 0; ni < NPB; ni++) {
                    float4 xv = *(const float4*)&xs[ni][h * 32 + d4 * 4];
                    acc[ni].x += xv.x*w0.x + xv.y*w1.x + xv.z*w2.x + xv.w*w3.x;
                    acc[ni].y += xv.x*w0.y + xv.y*w1.y + xv.z*w2.y + xv.w*w3.y;
                    acc[ni].z += xv.x*w0.z + xv.y*w1.z + xv.z*w2.z + xv.w*w3.z;
                    acc[ni].w += xv.x*w0.w + xv.y*w1.w + xv.z*w2.w + xv.w*w3.w;
                }
            }
            #pragma unroll
            for (int ni = 0; ni < NPB; ni++) {
                if (which == 0) *(float4*)&qsh[ni][off] = acc[ni];
                else            *(float4*)&g_KV[nidx[ni]*2*DD + kvoff] = acc[ni];
            }
        } else {
            #pragma unroll 1
            for (int ni = 0; ni < NPB; ni++) {
                int tn = ntype[nidx[ni]];
                const float* W = Wb + ((tn * HH + h) << 10) + c4 * 4;
                float4 a = make_float4(0.f, 0.f, 0.f, 0.f);
                #pragma unroll
                for (int d4 = 0; d4 < 8; d4++) {
                    float4 w0 = *(const float4*)(W + ((d4 * 4 + 0) << 5));
                    float4 w1 = *(const float4*)(W + ((d4 * 4 + 1) << 5));
                    float4 w2 = *(const float4*)(W + ((d4 * 4 + 2) << 5));
                    float4 w3 = *(const float4*)(W + ((d4 * 4 + 3) << 5));
                    float4 xv = *(const float4*)&xs[ni][h * 32 + d4 * 4];
                    a.x += xv.x*w0.x + xv.y*w1.x + xv.z*w2.x + xv.w*w3.x;
                    a.y += xv.x*w0.y + xv.y*w1.y + xv.z*w2.y + xv.w*w3.y;
                    a.z += xv.x*w0.z + xv.y*w1.z + xv.z*w2.z + xv.w*w3.z;
                    a.w += xv.x*w0.w + xv.y*w1.w + xv.z*w2.w + xv.w*w3.w;
                }
                if (which == 0) *(float4*)&qsh[ni][off] = a;
                else            *(float4*)&g_KV[nidx[ni]*2*DD + kvoff] = a;
            }
        }
    }
    __syncthreads();

    if (t < 192) {
        int et = t >> 6;
        const float* W = wet_l + ((et * HH + h) << 10) + c4 * 4;
        float c = mu_l[h * TEE + et] * 0.17677669529663687f;
        float4 acc[NPB];
        #pragma unroll
        for (int ni = 0; ni < NPB; ni++) acc[ni] = make_float4(0.f, 0.f, 0.f, 0.f);
        #pragma unroll
        for (int e4 = 0; e4 < 8; e4++) {
            float4 w0 = *(const float4*)(W + ((e4 * 4 + 0) << 5));
            float4 w1 = *(const float4*)(W + ((e4 * 4 + 1) << 5));
            float4 w2 = *(const float4*)(W + ((e4 * 4 + 2) << 5));
            float4 w3 = *(const float4*)(W + ((e4 * 4 + 3) << 5));
            #pragma unroll
            for (int ni = 0; ni < NPB; ni++) {
                float4 xv = *(const float4*)&qsh[ni][h * 32 + e4 * 4];
                acc[ni].x += xv.x*w0.x + xv.y*w1.x + xv.z*w2.x + xv.w*w3.x;
                acc[ni].y += xv.x*w0.y + xv.y*w1.y + xv.z*w2.y + xv.w*w3.y;
                acc[ni].z += xv.x*w0.z + xv.y*w1.z + xv.z*w2.z + xv.w*w3.z;
                acc[ni].w += xv.x*w0.w + xv.y*w1.w + xv.z*w2.w + xv.w*w3.w;
            }
        }
        int off = h * 32 + c4 * 4;
        #pragma unroll
        for (int ni = 0; ni < NPB; ni++) {
            float4 o;
            o.x = acc[ni].x * c; o.y = acc[ni].y * c;
            o.z = acc[ni].z * c; o.w = acc[ni].w * c;
            *(float4*)&g_QW[(nidx[ni] * TEE + et) * DD + off] = o;
        }
    }
}

// -------- edge attention (R9 version, measured 75.2us/layer) ------------------
__device__ __forceinline__ float edge_score(int pk, int base,
    const float4& q0a, const float4& q0b, const float4& q1a, const float4& q1b,
    const float4& q2a, const float4& q2b, float4& va, float4& vb) {
    int src = pk & 0xFFFFFF;
    int et  = pk >> 24;
    const float* kp = &g_KV[src * 2 * DD + base];
    float4 ka = *(const float4*)kp, kb = *(const float4*)(kp + 4);
    va = *(const float4*)(kp + DD); vb = *(const float4*)(kp + DD + 4);
    float4 qa = (et == 0) ? q0a : ((et == 1) ? q1a : q2a);
    float4 qb = (et == 0) ? q0b : ((et == 1) ? q1b : q2b);
    float p = ka.x*qa.x + ka.y*qa.y + ka.z*qa.z + ka.w*qa.w
            + kb.x*qb.x + kb.y*qb.y + kb.z*qb.z + kb.w*qb.w;
    p += __shfl_xor_sync(0xffffffffu, p, 1);
    p += __shfl_xor_sync(0xffffffffu, p, 2);
    return p;
}

__global__ void k_attn(int n_nodes) {
    int w = (blockIdx.x * blockDim.x + threadIdx.x) >> 5;
    if (w >= n_nodes) return;
    int l = threadIdx.x & 31;
    if (l == 0) g_cursor[w] = 0;
    int base = ((l >> 2) << 5) + ((l & 3) << 3);

    const float* qwp = &g_QW[(w * 3) * DD + base];
    float4 q0a = *(const float4*)(qwp);
    float4 q0b = *(const float4*)(qwp + 4);
    float4 q1a = *(const float4*)(qwp + DD);
    float4 q1b = *(const float4*)(qwp + DD + 4);
    float4 q2a = *(const float4*)(qwp + 2 * DD);
    float4 q2b = *(const float4*)(qwp + 2 * DD + 4);

    float m = -1e30f, s = 0.f;
    float a0=0,a1=0,a2=0,a3=0,a4=0,a5=0,a6=0,a7=0;
    int r0 = g_rowptr[w], r1 = g_rowptr[w + 1];
    int i = r0;
    for (; i + 4 <= r1; i += 4) {
        int pk0 = g_cpack[i],   pk1 = g_cpack[i+1];
        int pk2 = g_cpack[i+2], pk3 = g_cpack[i+3];
        float4 v0a, v0b, v1a, v1b, v2a, v2b, v3a, v3b;
        float p0 = edge_score(pk0, base, q0a,q0b,q1a,q1b,q2a,q2b, v0a, v0b);
        float p1 = edge_score(pk1, base, q0a,q0b,q1a,q1b,q2a,q2b, v1a, v1b);
        float p2 = edge_score(pk2, base, q0a,q0b,q1a,q1b,q2a,q2b, v2a, v2b);
        float p3 = edge_score(pk3, base, q0a,q0b,q1a,q1b,q2a,q2b, v3a, v3b);
        float mn = fmaxf(fmaxf(m, fmaxf(p0, p1)), fmaxf(p2, p3));
        float f  = __expf(m - mn);
        float e0 = __expf(p0 - mn);
        float e1 = __expf(p1 - mn);
        float e2 = __expf(p2 - mn);
        float e3 = __expf(p3 - mn);
        m = mn;
        s = s * f + (e0 + e1) + (e2 + e3);
        a0 = a0*f + e0*v0a.x + e1*v1a.x + e2*v2a.x + e3*v3a.x;
        a1 = a1*f + e0*v0a.y + e1*v1a.y + e2*v2a.y + e3*v3a.y;
        a2 = a2*f + e0*v0a.z + e1*v1a.z + e2*v2a.z + e3*v3a.z;
        a3 = a3*f + e0*v0a.w + e1*v1a.w + e2*v2a.w + e3*v3a.w;
        a4 = a4*f + e0*v0b.x + e1*v1b.x + e2*v2b.x + e3*v3b.x;
        a5 = a5*f + e0*v0b.y + e1*v1b.y + e2*v2b.y + e3*v3b.y;
        a6 = a6*f + e0*v0b.z + e1*v1b.z + e2*v2b.z + e3*v3b.z;
        a7 = a7*f + e0*v0b.w + e1*v1b.w + e2*v2b.w + e3*v3b.w;
    }
    for (; i < r1; i++) {
        float4 va, vb;
        float p = edge_score(g_cpack[i], base, q0a,q0b,q1a,q1b,q2a,q2b, va, vb);
        float mn = fmaxf(m, p);
        float f  = __expf(m - mn);
        float e  = __expf(p - mn);
        m = mn;
        s = s * f + e;
        a0 = a0*f + e*va.x; a1 = a1*f + e*va.y; a2 = a2*f + e*va.z; a3 = a3*f + e*va.w;
        a4 = a4*f + e*vb.x; a5 = a5*f + e*vb.y; a6 = a6*f + e*vb.z; a7 = a7*f + e*vb.w;
    }
    float inv = 1.0f / (s + 1e-10f);
    float o[8] = { a0*inv, a1*inv, a2*inv, a3*inv, a4*inv, a5*inv, a6*inv, a7*inv };
    __nv_bfloat16 h[8], lo[8];
    #pragma unroll
    for (int q = 0; q < 8; q++) split_bf16(o[q], h[q], lo[q]);
    *(uint4*)&g_aggH[w * DD + base] = *(uint4*)h;
    *(uint4*)&g_aggL[w * DD + base] = *(uint4*)lo;
}

// ============== pipelined tensor-core GEMM (bf16x3, cp.async) ================
#define PADB  80
#define TILEB 10240
#define SM_AH 0
#define SM_AL (TILEB)
#define SM_BH (2*TILEB)
#define SM_BL (3*TILEB)
#define STAGEB (4*TILEB)
#define GEMM_SMEM (2*STAGEB)

__device__ __forceinline__ void gemm_load_stage(
    uint32_t smb, int stage,
    const __nv_bfloat16* __restrict__ Ahi, const __nv_bfloat16* __restrict__ Alo,
    const __nv_bfloat16* __restrict__ Bhi, const __nv_bfloat16* __restrict__ Blo,
    int row0, int col0, int k0, int M, int K, int tid)
{
    uint32_t sp = smb + stage * STAGEB;
    #pragma unroll
    for (int it = 0; it < 2; it++) {
        int idx = tid + it * 256;
        int row = idx >> 2, seg = idx & 3;
        uint32_t off = row * PADB + seg * 16;
        size_t goff = (size_t)(row0 + row) * K + k0 + seg * 8;
        bool v = (row0 + row) < M;
        cp16z(sp + SM_AH + off, Ahi + goff, v);
        cp16z(sp + SM_AL + off, Alo + goff, v);
    }
    #pragma unroll
    for (int it = 0; it < 2; it++) {
        int idx = tid + it * 256;
        int n = idx >> 2, seg = idx & 3;
        uint32_t off = n * PADB + seg * 16;
        size_t goff = (size_t)(col0 + n) * K + k0 + seg * 8;
        cp16z(sp + SM_BH + off, Bhi + goff, true);
        cp16z(sp + SM_BL + off, Blo + goff, true);
    }
}

__global__ void __launch_bounds__(256, 2) k_gemm_mma(
    const __nv_bfloat16* __restrict__ Ahi, const __nv_bfloat16* __restrict__ Alo,
    const __nv_bfloat16* __restrict__ Bhi, const __nv_bfloat16* __restrict__ Blo,
    const float* __restrict__ bias, float* __restrict__ C,
    __nv_bfloat16* __restrict__ Chi, __nv_bfloat16* __restrict__ Clo,
    int M, int N, int K, int out_mode)
{
    extern __shared__ __align__(16) char smem[];
    uint32_t smb = smem_to_u32(smem);
    int tid = threadIdx.x, wid = tid >> 5, lane = tid & 31;
    int row0 = blockIdx.y * 128, col0 = blockIdx.x * 128;
    int wm = wid & 3, wn = wid >> 2;

    float acc[2][8][4];
    #pragma unroll
    for (int a = 0; a < 2; a++)
        #pragma unroll
        for (int b = 0; b < 8; b++)
            #pragma unroll
            for (int c = 0; c < 4; c++) acc[a][b][c] = 0.f;

    uint32_t a_row  = wm * 32 + (lane & 15);
    uint32_t a_col8 = (lane >> 4) * 8;
    uint32_t b_row  = wn * 64 + ((lane >> 4) & 1) * 8 + (lane & 7);
    uint32_t b_col8 = ((lane >> 3) & 1) * 8;

    int nc = K >> 5;
    gemm_load_stage(smb, 0, Ahi, Alo, Bhi, Blo, row0, col0, 0, M, K, tid);
    CP_COMMIT();

    for (int c = 0; c < nc; c++) {
        if (c + 1 < nc) {
            gemm_load_stage(smb, (c + 1) & 1, Ahi, Alo, Bhi, Blo,
                            row0, col0, (c + 1) << 5, M, K, tid);
            CP_COMMIT();
            CP_WAIT1();
        } else {
            CP_WAIT0();
        }
        __syncthreads();
        uint32_t sp = smb + (c & 1) * STAGEB;
        #pragma unroll
        for (int kk = 0; kk < 2; kk++) {
            uint32_t ah[2][4], al[2][4];
            #pragma unroll
            for (int mt = 0; mt < 2; mt++) {
                uint32_t off = (a_row + mt * 16) * PADB + (kk * 16 + a_col8) * 2;
                ldmat_x4(ah[mt], sp + SM_AH + off);
                ldmat_x4(al[mt], sp + SM_AL + off);
            }
            #pragma unroll
            for (int p = 0; p < 4; p++) {
                uint32_t bh[4], bl[4];
                uint32_t off = (b_row + p * 16) * PADB + (kk * 16 + b_col8) * 2;
                ldmat_x4(bh, sp + SM_BH + off);
                ldmat_x4(bl, sp + SM_BL + off);
                #pragma unroll
                for (int mt = 0; mt < 2; mt++) {
                    mma_bf16(acc[mt][p * 2 + 0], ah[mt], &bh[0]);
                    mma_bf16(acc[mt][p * 2 + 1], ah[mt], &bh[2]);
                    mma_bf16(acc[mt][p * 2 + 0], ah[mt], &bl[0]);
                    mma_bf16(acc[mt][p * 2 + 1], ah[mt], &bl[2]);
                    mma_bf16(acc[mt][p * 2 + 0], al[mt], &bh[0]);
                    mma_bf16(acc[mt][p * 2 + 1], al[mt], &bh[2]);
                }
            }
        }
        __syncthreads();
    }

    int g = lane >> 2, tg = lane & 3;
    #pragma unroll
    for (int mt = 0; mt < 2; mt++) {
        int r_hi = row0 + wm * 32 + mt * 16 + g;
        #pragma unroll
        for (int j = 0; j < 8; j++) {
            int cc = col0 + wn * 64 + j * 8 + tg * 2;
            float bx = bias[cc], by = bias[cc + 1];
            #pragma unroll
            for (int half = 0; half < 2; half++) {
                int r = r_hi + half * 8;
                if (r >= M) continue;
                float ox = acc[mt][j][half * 2 + 0] + bx;
                float oy = acc[mt][j][half * 2 + 1] + by;
                if (out_mode == 2) {
                    ox = gelu_f(ox); oy = gelu_f(oy);
                    __nv_bfloat16 hx, lx, hy, ly;
                    split_bf16(ox, hx, lx);
                    split_bf16(oy, hy, ly);
                    __nv_bfloat162 hv; hv.x = hx; hv.y = hy;
                    __nv_bfloat162 lv; lv.x = lx; lv.y = ly;
                    *(__nv_bfloat162*)&Chi[(size_t)r * N + cc] = hv;
                    *(__nv_bfloat162*)&Clo[(size_t)r * N + cc] = lv;
                } else {
                    float2 o; o.x = ox; o.y = oy;
                    *(float2*)&C[(size_t)r * N + cc] = o;
                }
            }
        }
    }
}

// -------- residual + LayerNorm: warp per node ---------------------------------
__global__ void k_lnres(const float* __restrict__ xin, const float* __restrict__ yin,
                        const float* __restrict__ g, const float* __restrict__ b,
                        float* __restrict__ xout,
                        __nv_bfloat16* __restrict__ outH, __nv_bfloat16* __restrict__ outL,
                        int n_nodes) {
    int w = (blockIdx.x * blockDim.x + threadIdx.x) >> 5;
    if (w >= n_nodes) return;
    int lane = threadIdx.x & 31;
    int off = w * DD + lane * 8;

    float4 va = *(const float4*)&xin[off];
    float4 vb = *(const float4*)&xin[off + 4];
    if (yin) {
        float4 ya = *(const float4*)&yin[off];
        float4 yb = *(const float4*)&yin[off + 4];
        va.x += ya.x; va.y += ya.y; va.z += ya.z; va.w += ya.w;
        vb.x += yb.x; vb.y += yb.y; vb.z += yb.z; vb.w += yb.w;
    }
    float sum = va.x + va.y + va.z + va.w + vb.x + vb.y + vb.z + vb.w;
    #pragma unroll
    for (int o = 16; o; o >>= 1) sum += __shfl_xor_sync(0xffffffffu, sum, o);
    float mean = sum * (1.0f / 256.0f);
    float d[8] = { va.x-mean, va.y-mean, va.z-mean, va.w-mean,
                   vb.x-mean, vb.y-mean, vb.z-mean, vb.w-mean };
    float vs = 0.f;
    #pragma unroll
    for (int q = 0; q < 8; q++) vs += d[q] * d[q];
    #pragma unroll
    for (int o = 16; o; o >>= 1) vs += __shfl_xor_sync(0xffffffffu, vs, o);
    float inv = rsqrtf(vs * (1.0f / 256.0f) + 1e-5f);

    float4 ga = *(const float4*)&g[lane * 8];
    float4 gb = *(const float4*)&g[lane * 8 + 4];
    float4 ba = *(const float4*)&b[lane * 8];
    float4 bb = *(const float4*)&b[lane * 8 + 4];
    float r[8];
    r[0] = d[0]*inv*ga.x + ba.x; r[1] = d[1]*inv*ga.y + ba.y;
    r[2] = d[2]*inv*ga.z + ba.z; r[3] = d[3]*inv*ga.w + ba.w;
    r[4] = d[4]*inv*gb.x + bb.x; r[5] = d[5]*inv*gb.y + bb.y;
    r[6] = d[6]*inv*gb.z + bb.z; r[7] = d[7]*inv*gb.w + bb.w;
    *(float4*)&xout[off]     = make_float4(r[0], r[1], r[2], r[3]);
    *(float4*)&xout[off + 4] = make_float4(r[4], r[5], r[6], r[7]);
    if (outH) {
        __nv_bfloat16 h[8], lo[8];
        #pragma unroll
        for (int q = 0; q < 8; q++) split_bf16(r[q], h[q], lo[q]);
        *(uint4*)&outH[off] = *(uint4*)h;
        *(uint4*)&outL[off] = *(uint4*)lo;
    }
}

// ---------------- host ---------------------------------------------------------
extern "C" void kernel_launch(void* const* d_in, const int* in_sizes, int n_in,
                              void* d_out, int out_size) {
    const float* x     = (const float*)d_in[0];
    const int*   ei    = (const int*)  d_in[1];
    const int*   etype = (const int*)  d_in[2];
    const int*   ntype = (const int*)  d_in[3];
    const float* WQ    = (const float*)d_in[4];
    const float* WK    = (const float*)d_in[5];
    const float* WV    = (const float*)d_in[6];
    const float* WE    = (const float*)d_in[7];
    const float* mu    = (const float*)d_in[8];
    const float* Wo    = (const float*)d_in[9];
    const float* bo    = (const float*)d_in[10];
    const float* ln1g  = (const float*)d_in[11];
    const float* ln1b  = (const float*)d_in[12];
    const float* ln2g  = (const float*)d_in[13];
    const float* ln2b  = (const float*)d_in[14];
    const float* w1    = (const float*)d_in[15];
    const float* b1    = (const float*)d_in[16];
    const float* w2    = (const float*)d_in[17];
    const float* b2    = (const float*)d_in[18];
    const float* outg  = (const float*)d_in[19];
    const float* outb  = (const float*)d_in[20];

    int N = in_sizes[0] / DD;
    int E = in_sizes[2];

    float *px, *py, *pwet;
    cudaGetSymbolAddress((void**)&px,   g_x);
    cudaGetSymbolAddress((void**)&py,   g_y);
    cudaGetSymbolAddress((void**)&pwet, g_WET);

    __nv_bfloat16 *pAggH, *pAggL, *pXH, *pXL, *pFH, *pFL;
    cudaGetSymbolAddress((void**)&pAggH, g_aggH);
    cudaGetSymbolAddress((void**)&pAggL, g_aggL);
    cudaGetSymbolAddress((void**)&pXH,   g_xH);
    cudaGetSymbolAddress((void**)&pXL,   g_xL);
    cudaGetSymbolAddress((void**)&pFH,   g_ffnH);
    cudaGetSymbolAddress((void**)&pFL,   g_ffnL);

    __nv_bfloat16 *pWoH, *pWoL, *pW1H, *pW1L, *pW2H, *pW2L;
    cudaGetSymbolAddress((void**)&pWoH, g_WoT_hi);
    cudaGetSymbolAddress((void**)&pWoL, g_WoT_lo);
    cudaGetSymbolAddress((void**)&pW1H, g_W1T_hi);
    cudaGetSymbolAddress((void**)&pW1L, g_W1T_lo);
    cudaGetSymbolAddress((void**)&pW2H, g_W2T_hi);
    cudaGetSymbolAddress((void**)&pW2L, g_W2T_lo);

    cudaFuncSetAttribute(k_gemm_mma, cudaFuncAttributeMaxDynamicSharedMemorySize, GEMM_SMEM);

    // preprocessing (3 launches; x copy folded into k_count)
    k_count<<<1250, 256>>>(x, ei, ntype, WE, Wo, w1, w2, N, E);
    k_scan<<<1, 1024>>>(N);
    k_scat<<<(E + 255) / 256, 256>>>(ei, etype, ntype, N, E);

    int mtiles = (N + 127) / 128;
    int lnblocks = (N + 7) / 8;

    for (int l = 0; l < LLAY; l++) {
        const float* wq  = WQ + (size_t)l * TNN * HH * 1024;
        const float* wk  = WK + (size_t)l * TNN * HH * 1024;
        const float* wv  = WV + (size_t)l * TNN * HH * 1024;
        const float* mul = mu + (size_t)l * HH * TEE;
        const float* bol = bo + (size_t)l * DD;
        const float* b1l = b1 + (size_t)l * FF;
        const float* b2l = b2 + (size_t)l * DD;
        const float* wetl = pwet + (size_t)l * TEE * HH * 1024;

        k_qkv<<<(N + NPB - 1) / NPB, 256>>>(wq, wk, wv, wetl, mul, ntype, N);
        k_attn<<<(N * 32 + 255) / 256, 256>>>(N);

        {
            dim3 grid(DD / 128, mtiles);
            k_gemm_mma<<<grid, 256, GEMM_SMEM>>>(pAggH, pAggL,
                pWoH + (size_t)l * DD * DD, pWoL + (size_t)l * DD * DD,
                bol, py, (__nv_bfloat16*)nullptr, (__nv_bfloat16*)nullptr,
                N, DD, DD, 0);
        }
        k_lnres<<<lnblocks, 256>>>(px, py, ln1g + l * DD, ln1b + l * DD, px, pXH, pXL, N);

        {
            dim3 grid(FF / 128, mtiles);
            k_gemm_mma<<<grid, 256, GEMM_SMEM>>>(pXH, pXL,
                pW1H + (size_t)l * FF * DD, pW1L + (size_t)l * FF * DD,
                b1l, (float*)nullptr, pFH, pFL, N, FF, DD, 2);
        }
        {
            dim3 grid(DD / 128, mtiles);
            k_gemm_mma<<<grid, 256, GEMM_SMEM>>>(pFH, pFL,
                pW2H + (size_t)l * DD * FF, pW2L + (size_t)l * DD * FF,
                b2l, py, (__nv_bfloat16*)nullptr, (__nv_bfloat16*)nullptr,
                N, DD, FF, 0);
        }
        k_lnres<<<lnblocks, 256>>>(px, py, ln2g + l * DD, ln2b + l * DD, px,
                                   (__nv_bfloat16*)nullptr, (__nv_bfloat16*)nullptr, N);
    }

    k_lnres<<<lnblocks, 256>>>(px, (const float*)nullptr, outg, outb, (float*)d_out,
                               (__nv_bfloat16*)nullptr, (__nv_bfloat16*)nullptr, N);
}

// round 15
// speedup vs baseline: 1.1605x; 1.0128x over previous
#include <cuda_runtime.h>
#include <cuda_bf16.h>
#include <math.h>
#include <stdint.h>

#define NMAX 20000
#define EMAX 320000
#define DD   256
#define HH   8
#define HDD  32
#define TEE  3
#define TNN  4
#define LLAY 3
#define FF   1024
#define NPB  8
#define DBK  64          // degree buckets for attn load balancing

// ---------------- scratch (device globals; zero-initialized at load) --------
__device__ float g_x   [NMAX*DD];
__device__ float g_KV  [NMAX*2*DD];
__device__ float g_QW  [NMAX*TEE*DD];
__device__ float g_y   [NMAX*DD];
__device__ int   g_rowptr[NMAX+1];
__device__ int   g_cursor[NMAX];      // zero at entry (re-zeroed by k_attn)
__device__ int   g_cpack [EMAX];
__device__ int   g_order [NMAX];      // type-sorted (for k_qkv)
__device__ int   g_aorder[NMAX];      // degree-sorted desc (for k_attn)
__device__ int   g_tcnt  [TNN];       // zero at entry (re-zeroed by k_qkv)
__device__ int   g_tcur  [TNN];
__device__ int   g_dcur  [DBK];       // degree-bucket cursors (set by k_scan)
__device__ float g_WET [LLAY*TEE*HH*HDD*HDD];

__device__ __nv_bfloat16 g_aggH[NMAX*DD];
__device__ __nv_bfloat16 g_aggL[NMAX*DD];
__device__ __nv_bfloat16 g_xH  [NMAX*DD];
__device__ __nv_bfloat16 g_xL  [NMAX*DD];
__device__ __nv_bfloat16 g_ffnH[NMAX*FF];
__device__ __nv_bfloat16 g_ffnL[NMAX*FF];

__device__ __nv_bfloat16 g_WoT_hi[LLAY*DD*DD];
__device__ __nv_bfloat16 g_WoT_lo[LLAY*DD*DD];
__device__ __nv_bfloat16 g_W1T_hi[LLAY*FF*DD];
__device__ __nv_bfloat16 g_W1T_lo[LLAY*FF*DD];
__device__ __nv_bfloat16 g_W2T_hi[LLAY*DD*FF];
__device__ __nv_bfloat16 g_W2T_lo[LLAY*DD*FF];

// ---------------- helpers ------------------------------------------------
__device__ __forceinline__ float gelu_f(float v) {
    return 0.5f * v * (1.0f + erff(v * 0.70710678118654752f));
}
__device__ __forceinline__ uint32_t smem_to_u32(const void* p) {
    uint32_t a;
    asm("{ .reg .u64 t; cvta.to.shared.u64 t, %1; cvt.u32.u64 %0, t; }" : "=r"(a) : "l"(p));
    return a;
}
__device__ __forceinline__ void ldmat_x4(uint32_t* r, uint32_t addr) {
    asm volatile("ldmatrix.sync.aligned.m8n8.x4.shared.b16 {%0,%1,%2,%3}, [%4];"
        : "=r"(r[0]), "=r"(r[1]), "=r"(r[2]), "=r"(r[3]) : "r"(addr));
}
__device__ __forceinline__ void mma_bf16(float* d, const uint32_t* a, const uint32_t* b) {
    asm volatile("mma.sync.aligned.m16n8k16.row.col.f32.bf16.bf16.f32 "
        "{%0,%1,%2,%3}, {%4,%5,%6,%7}, {%8,%9}, {%0,%1,%2,%3};"
        : "+f"(d[0]), "+f"(d[1]), "+f"(d[2]), "+f"(d[3])
        : "r"(a[0]), "r"(a[1]), "r"(a[2]), "r"(a[3]), "r"(b[0]), "r"(b[1]));
}
__device__ __forceinline__ void cp16z(uint32_t dst, const void* src, bool valid) {
    int sz = valid ? 16 : 0;
    asm volatile("cp.async.cg.shared.global [%0], [%1], 16, %2;"
        :: "r"(dst), "l"(src), "r"(sz));
}
#define CP_COMMIT()  asm volatile("cp.async.commit_group;" ::: "memory")
#define CP_WAIT1()   asm volatile("cp.async.wait_group 1;" ::: "memory")
#define CP_WAIT0()   asm volatile("cp.async.wait_group 0;" ::: "memory")

__device__ __forceinline__ void split_bf16(float v, __nv_bfloat16& h, __nv_bfloat16& l) {
    h = __float2bfloat16_rn(v);
    l = __float2bfloat16_rn(v - __bfloat162float(h));
}

// ======= preprocessing (3 launches) ===========================================
__device__ __forceinline__ void splitT_one(const float* W, __nv_bfloat16* hi,
                                           __nv_bfloat16* lo, int K, int N, int i) {
    int k = i / N, n = i % N;
    float w = W[i];
    __nv_bfloat16 h, l; split_bf16(w, h, l);
    hi[(size_t)n * K + k] = h;
    lo[(size_t)n * K + k] = l;
}

// launch #1: x copy + edge/node counting + all weight prep
__global__ void k_count(const float* __restrict__ x,
                        const int* __restrict__ ei, const int* __restrict__ nt,
                        const float* __restrict__ WE, const float* __restrict__ Wo,
                        const float* __restrict__ w1, const float* __restrict__ w2,
                        int n, int E) {
    int gs = gridDim.x * blockDim.x;
    int gid = blockIdx.x * blockDim.x + threadIdx.x;
    for (int i = gid; i < n * DD / 4; i += gs)
        ((float4*)g_x)[i] = ((const float4*)x)[i];
    for (int i = gid; i < E; i += gs) atomicAdd(&g_cursor[ei[E + i]], 1);
    for (int i = gid; i < n; i += gs) atomicAdd(&g_tcnt[nt[i]], 1);
    for (int i = gid; i < LLAY * TEE * HH * HDD * HDD; i += gs) {
        int d = i & 31, e = (i >> 5) & 31, base = i >> 10;
        g_WET[i] = WE[(base << 10) + (d << 5) + e];
    }
    for (int i = gid; i < LLAY * DD * DD; i += gs) {
        int l = i / (DD * DD), j = i % (DD * DD);
        splitT_one(Wo + (size_t)l * DD * DD, g_WoT_hi + (size_t)l * DD * DD,
                   g_WoT_lo + (size_t)l * DD * DD, DD, DD, j);
    }
    for (int i = gid; i < LLAY * DD * FF; i += gs) {
        int l = i / (DD * FF), j = i % (DD * FF);
        splitT_one(w1 + (size_t)l * DD * FF, g_W1T_hi + (size_t)l * FF * DD,
                   g_W1T_lo + (size_t)l * FF * DD, DD, FF, j);
    }
    for (int i = gid; i < LLAY * FF * DD; i += gs) {
        int l = i / (FF * DD), j = i % (FF * DD);
        splitT_one(w2 + (size_t)l * FF * DD, g_W2T_hi + (size_t)l * DD * FF,
                   g_W2T_lo + (size_t)l * DD * FF, FF, DD, j);
    }
}

// launch #2: shfl scan + rowptr + type bases + degree-bucket bases
__global__ void k_scan(int n) {
    __shared__ int wsum[32];
    __shared__ int dhist[DBK];
    int t = threadIdx.x;
    int lane = t & 31, wid = t >> 5;
    int chunk = (n + 1023) / 1024;
    int start = t * chunk;
    int end = start + chunk; if (end > n) end = n;

    if (t < DBK) dhist[t] = 0;

    int s = 0;
    for (int j = start; j < end; j++) s += g_cursor[j];
    int ps = s;
    #pragma unroll
    for (int o = 1; o < 32; o <<= 1) {
        int v = __shfl_up_sync(0xffffffffu, ps, o);
        if (lane >= o) ps += v;
    }
    if (lane == 31) wsum[wid] = ps;
    __syncthreads();
    if (wid == 0) {
        int pv = wsum[lane];
        #pragma unroll
        for (int o = 1; o < 32; o <<= 1) {
            int u = __shfl_up_sync(0xffffffffu, pv, o);
            if (lane >= o) pv += u;
        }
        wsum[lane] = pv;
    }
    __syncthreads();
    int base = ps - s + ((wid > 0) ? wsum[wid - 1] : 0);
    int run = base;
    for (int j = start; j < end; j++) {
        int c = g_cursor[j];
        g_rowptr[j] = run;
        g_cursor[j] = run;
        run += c;
        int b = (c < DBK) ? c : (DBK - 1);
        atomicAdd(&dhist[b], 1);
    }
    if (t == 0) {
        g_rowptr[n] = wsum[31];
        int c = 0;
        for (int k = 0; k < TNN; k++) { g_tcur[k] = c; c += g_tcnt[k]; }
        // degree buckets in DESCENDING degree order
        int d = 0;
        for (int b = DBK - 1; b >= 0; b--) { g_dcur[b] = d; d += dhist[b]; }
    }
}

// launch #3: edge scatter + type-order scatter + degree-order scatter
__global__ void k_scat(const int* __restrict__ ei, const int* __restrict__ et,
                       const int* __restrict__ nt, int n, int E) {
    int gs = gridDim.x * blockDim.x;
    int gid = blockIdx.x * blockDim.x + threadIdx.x;
    for (int i = gid; i < E; i += gs) {
        int dst = ei[E + i];
        int p = atomicAdd(&g_cursor[dst], 1);
        g_cpack[p] = ei[i] | (et[i] << 24);
    }
    for (int i = gid; i < n; i += gs) {
        int p = atomicAdd(&g_tcur[nt[i]], 1);
        g_order[p] = i;
        int deg = g_rowptr[i + 1] - g_rowptr[i];
        int b = (deg < DBK) ? deg : (DBK - 1);
        int q = atomicAdd(&g_dcur[b], 1);
        g_aorder[q] = i;
    }
}

// -------- per-node QKV + QW (R9 version, measured 86.5us/layer) ---------------
__global__ void __launch_bounds__(256) k_qkv(
    const float* __restrict__ wq, const float* __restrict__ wk,
    const float* __restrict__ wv, const float* __restrict__ wet_l,
    const float* __restrict__ mu_l, const int* __restrict__ ntype,
    int n_nodes) {
    __shared__ float xs [NPB][DD];
    __shared__ float qsh[NPB][DD];
    int t = threadIdx.x;
    if (blockIdx.x == 0 && t < TNN) { g_tcnt[t] = 0; g_tcur[t] = 0; }
    int slot0 = blockIdx.x * NPB;
    int nv = n_nodes - slot0; if (nv > NPB) nv = NPB;

    int nidx[NPB];
    #pragma unroll
    for (int ni = 0; ni < NPB; ni++) {
        int n = g_order[(ni < nv) ? (slot0 + ni) : slot0];
        nidx[ni] = n;
        xs[ni][t] = g_x[n * DD + t];
    }
    int tn0 = ntype[nidx[0]];
    bool uni = true;
    #pragma unroll
    for (int ni = 1; ni < NPB; ni++) uni &= (ntype[nidx[ni]] == tn0);
    __syncthreads();

    int v  = t & 63;
    int h  = v >> 3;
    int c4 = v & 7;

    if (t < 192) {
        int which = t >> 6;
        const float* Wb = (which == 0 ? wq : (which == 1 ? wk : wv));
        int off = h * 32 + c4 * 4;
        int kvoff = (which == 1) ? off : (off + DD);
        if (uni) {
            const float* W = Wb + ((tn0 * HH + h) << 10) + c4 * 4;
            float4 acc[NPB];
            #pragma unroll
            for (int ni = 0; ni < NPB; ni++) acc[ni] = make_float4(0.f, 0.f, 0.f, 0.f);
            #pragma unroll
            for (int d4 = 0; d4 < 8; d4++) {
                float4 w0 = *(const float4*)(W + ((d4 * 4 + 0) << 5));
                float4 w1 = *(const float4*)(W + ((d4 * 4 + 1) << 5));
                float4 w2 = *(const float4*)(W + ((d4 * 4 + 2) << 5));
                float4 w3 = *(const float4*)(W + ((d4 * 4 + 3) << 5));
                #pragma unroll
                for (int ni = 0; ni < NPB; ni++) {
                    float4 xv = *(const float4*)&xs[ni][h * 32 + d4 * 4];
                    acc[ni].x += xv.x*w0.x + xv.y*w1.x + xv.z*w2.x + xv.w*w3.x;
                    acc[ni].y += xv.x*w0.y + xv.y*w1.y + xv.z*w2.y + xv.w*w3.y;
                    acc[ni].z += xv.x*w0.z + xv.y*w1.z + xv.z*w2.z + xv.w*w3.z;
                    acc[ni].w += xv.x*w0.w + xv.y*w1.w + xv.z*w2.w + xv.w*w3.w;
                }
            }
            #pragma unroll
            for (int ni = 0; ni < NPB; ni++) {
                if (which == 0) *(float4*)&qsh[ni][off] = acc[ni];
                else            *(float4*)&g_KV[nidx[ni]*2*DD + kvoff] = acc[ni];
            }
        } else {
            #pragma unroll 1
            for (int ni = 0; ni < NPB; ni++) {
                int tn = ntype[nidx[ni]];
                const float* W = Wb + ((tn * HH + h) << 10) + c4 * 4;
                float4 a = make_float4(0.f, 0.f, 0.f, 0.f);
                #pragma unroll
                for (int d4 = 0; d4 < 8; d4++) {
                    float4 w0 = *(const float4*)(W + ((d4 * 4 + 0) << 5));
                    float4 w1 = *(const float4*)(W + ((d4 * 4 + 1) << 5));
                    float4 w2 = *(const float4*)(W + ((d4 * 4 + 2) << 5));
                    float4 w3 = *(const float4*)(W + ((d4 * 4 + 3) << 5));
                    float4 xv = *(const float4*)&xs[ni][h * 32 + d4 * 4];
                    a.x += xv.x*w0.x + xv.y*w1.x + xv.z*w2.x + xv.w*w3.x;
                    a.y += xv.x*w0.y + xv.y*w1.y + xv.z*w2.y + xv.w*w3.y;
                    a.z += xv.x*w0.z + xv.y*w1.z + xv.z*w2.z + xv.w*w3.z;
                    a.w += xv.x*w0.w + xv.y*w1.w + xv.z*w2.w + xv.w*w3.w;
                }
                if (which == 0) *(float4*)&qsh[ni][off] = a;
                else            *(float4*)&g_KV[nidx[ni]*2*DD + kvoff] = a;
            }
        }
    }
    __syncthreads();

    if (t < 192) {
        int et = t >> 6;
        const float* W = wet_l + ((et * HH + h) << 10) + c4 * 4;
        float c = mu_l[h * TEE + et] * 0.17677669529663687f;
        float4 acc[NPB];
        #pragma unroll
        for (int ni = 0; ni < NPB; ni++) acc[ni] = make_float4(0.f, 0.f, 0.f, 0.f);
        #pragma unroll
        for (int e4 = 0; e4 < 8; e4++) {
            float4 w0 = *(const float4*)(W + ((e4 * 4 + 0) << 5));
            float4 w1 = *(const float4*)(W + ((e4 * 4 + 1) << 5));
            float4 w2 = *(const float4*)(W + ((e4 * 4 + 2) << 5));
            float4 w3 = *(const float4*)(W + ((e4 * 4 + 3) << 5));
            #pragma unroll
            for (int ni = 0; ni < NPB; ni++) {
                float4 xv = *(const float4*)&qsh[ni][h * 32 + e4 * 4];
                acc[ni].x += xv.x*w0.x + xv.y*w1.x + xv.z*w2.x + xv.w*w3.x;
                acc[ni].y += xv.x*w0.y + xv.y*w1.y + xv.z*w2.y + xv.w*w3.y;
                acc[ni].z += xv.x*w0.z + xv.y*w1.z + xv.z*w2.z + xv.w*w3.z;
                acc[ni].w += xv.x*w0.w + xv.y*w1.w + xv.z*w2.w + xv.w*w3.w;
            }
        }
        int off = h * 32 + c4 * 4;
        #pragma unroll
        for (int ni = 0; ni < NPB; ni++) {
            float4 o;
            o.x = acc[ni].x * c; o.y = acc[ni].y * c;
            o.z = acc[ni].z * c; o.w = acc[ni].w * c;
            *(float4*)&g_QW[(nidx[ni] * TEE + et) * DD + off] = o;
        }
    }
}

// -------- edge attention (R9 inner loop; degree-sorted node assignment) -------
__device__ __forceinline__ float edge_score(int pk, int base,
    const float4& q0a, const float4& q0b, const float4& q1a, const float4& q1b,
    const float4& q2a, const float4& q2b, float4& va, float4& vb) {
    int src = pk & 0xFFFFFF;
    int et  = pk >> 24;
    const float* kp = &g_KV[src * 2 * DD + base];
    float4 ka = *(const float4*)kp, kb = *(const float4*)(kp + 4);
    va = *(const float4*)(kp + DD); vb = *(const float4*)(kp + DD + 4);
    float4 qa = (et == 0) ? q0a : ((et == 1) ? q1a : q2a);
    float4 qb = (et == 0) ? q0b : ((et == 1) ? q1b : q2b);
    float p = ka.x*qa.x + ka.y*qa.y + ka.z*qa.z + ka.w*qa.w
            + kb.x*qb.x + kb.y*qb.y + kb.z*qb.z + kb.w*qb.w;
    p += __shfl_xor_sync(0xffffffffu, p, 1);
    p += __shfl_xor_sync(0xffffffffu, p, 2);
    return p;
}

__global__ void k_attn(int n_nodes) {
    int slot = (blockIdx.x * blockDim.x + threadIdx.x) >> 5;
    if (slot >= n_nodes) return;
    int w = g_aorder[slot];        // degree-sorted (desc) node assignment
    int l = threadIdx.x & 31;
    if (l == 0) g_cursor[w] = 0;
    int base = ((l >> 2) << 5) + ((l & 3) << 3);

    const float* qwp = &g_QW[(w * 3) * DD + base];
    float4 q0a = *(const float4*)(qwp);
    float4 q0b = *(const float4*)(qwp + 4);
    float4 q1a = *(const float4*)(qwp + DD);
    float4 q1b = *(const float4*)(qwp + DD + 4);
    float4 q2a = *(const float4*)(qwp + 2 * DD);
    float4 q2b = *(const float4*)(qwp + 2 * DD + 4);

    float m = -1e30f, s = 0.f;
    float a0=0,a1=0,a2=0,a3=0,a4=0,a5=0,a6=0,a7=0;
    int r0 = g_rowptr[w], r1 = g_rowptr[w + 1];
    int i = r0;
    for (; i + 4 <= r1; i += 4) {
        int pk0 = g_cpack[i],   pk1 = g_cpack[i+1];
        int pk2 = g_cpack[i+2], pk3 = g_cpack[i+3];
        float4 v0a, v0b, v1a, v1b, v2a, v2b, v3a, v3b;
        float p0 = edge_score(pk0, base, q0a,q0b,q1a,q1b,q2a,q2b, v0a, v0b);
        float p1 = edge_score(pk1, base, q0a,q0b,q1a,q1b,q2a,q2b, v1a, v1b);
        float p2 = edge_score(pk2, base, q0a,q0b,q1a,q1b,q2a,q2b, v2a, v2b);
        float p3 = edge_score(pk3, base, q0a,q0b,q1a,q1b,q2a,q2b, v3a, v3b);
        float mn = fmaxf(fmaxf(m, fmaxf(p0, p1)), fmaxf(p2, p3));
        float f  = __expf(m - mn);
        float e0 = __expf(p0 - mn);
        float e1 = __expf(p1 - mn);
        float e2 = __expf(p2 - mn);
        float e3 = __expf(p3 - mn);
        m = mn;
        s = s * f + (e0 + e1) + (e2 + e3);
        a0 = a0*f + e0*v0a.x + e1*v1a.x + e2*v2a.x + e3*v3a.x;
        a1 = a1*f + e0*v0a.y + e1*v1a.y + e2*v2a.y + e3*v3a.y;
        a2 = a2*f + e0*v0a.z + e1*v1a.z + e2*v2a.z + e3*v3a.z;
        a3 = a3*f + e0*v0a.w + e1*v1a.w + e2*v2a.w + e3*v3a.w;
        a4 = a4*f + e0*v0b.x + e1*v1b.x + e2*v2b.x + e3*v3b.x;
        a5 = a5*f + e0*v0b.y + e1*v1b.y + e2*v2b.y + e3*v3b.y;
        a6 = a6*f + e0*v0b.z + e1*v1b.z + e2*v2b.z + e3*v3b.z;
        a7 = a7*f + e0*v0b.w + e1*v1b.w + e2*v2b.w + e3*v3b.w;
    }
    for (; i < r1; i++) {
        float4 va, vb;
        float p = edge_score(g_cpack[i], base, q0a,q0b,q1a,q1b,q2a,q2b, va, vb);
        float mn = fmaxf(m, p);
        float f  = __expf(m - mn);
        float e  = __expf(p - mn);
        m = mn;
        s = s * f + e;
        a0 = a0*f + e*va.x; a1 = a1*f + e*va.y; a2 = a2*f + e*va.z; a3 = a3*f + e*va.w;
        a4 = a4*f + e*vb.x; a5 = a5*f + e*vb.y; a6 = a6*f + e*vb.z; a7 = a7*f + e*vb.w;
    }
    float inv = 1.0f / (s + 1e-10f);
    float o[8] = { a0*inv, a1*inv, a2*inv, a3*inv, a4*inv, a5*inv, a6*inv, a7*inv };
    __nv_bfloat16 h[8], lo[8];
    #pragma unroll
    for (int q = 0; q < 8; q++) split_bf16(o[q], h[q], lo[q]);
    *(uint4*)&g_aggH[w * DD + base] = *(uint4*)h;
    *(uint4*)&g_aggL[w * DD + base] = *(uint4*)lo;
}

// ============== pipelined tensor-core GEMM (bf16x3, cp.async) ================
#define PADB  80
#define TILEB 10240
#define SM_AH 0
#define SM_AL (TILEB)
#define SM_BH (2*TILEB)
#define SM_BL (3*TILEB)
#define STAGEB (4*TILEB)
#define GEMM_SMEM (2*STAGEB)

__device__ __forceinline__ void gemm_load_stage(
    uint32_t smb, int stage,
    const __nv_bfloat16* __restrict__ Ahi, const __nv_bfloat16* __restrict__ Alo,
    const __nv_bfloat16* __restrict__ Bhi, const __nv_bfloat16* __restrict__ Blo,
    int row0, int col0, int k0, int M, int K, int tid)
{
    uint32_t sp = smb + stage * STAGEB;
    #pragma unroll
    for (int it = 0; it < 2; it++) {
        int idx = tid + it * 256;
        int row = idx >> 2, seg = idx & 3;
        uint32_t off = row * PADB + seg * 16;
        size_t goff = (size_t)(row0 + row) * K + k0 + seg * 8;
        bool v = (row0 + row) < M;
        cp16z(sp + SM_AH + off, Ahi + goff, v);
        cp16z(sp + SM_AL + off, Alo + goff, v);
    }
    #pragma unroll
    for (int it = 0; it < 2; it++) {
        int idx = tid + it * 256;
        int n = idx >> 2, seg = idx & 3;
        uint32_t off = n * PADB + seg * 16;
        size_t goff = (size_t)(col0 + n) * K + k0 + seg * 8;
        cp16z(sp + SM_BH + off, Bhi + goff, true);
        cp16z(sp + SM_BL + off, Blo + goff, true);
    }
}

__global__ void __launch_bounds__(256, 2) k_gemm_mma(
    const __nv_bfloat16* __restrict__ Ahi, const __nv_bfloat16* __restrict__ Alo,
    const __nv_bfloat16* __restrict__ Bhi, const __nv_bfloat16* __restrict__ Blo,
    const float* __restrict__ bias, float* __restrict__ C,
    __nv_bfloat16* __restrict__ Chi, __nv_bfloat16* __restrict__ Clo,
    int M, int N, int K, int out_mode)
{
    extern __shared__ __align__(16) char smem[];
    uint32_t smb = smem_to_u32(smem);
    int tid = threadIdx.x, wid = tid >> 5, lane = tid & 31;
    int row0 = blockIdx.y * 128, col0 = blockIdx.x * 128;
    int wm = wid & 3, wn = wid >> 2;

    float acc[2][8][4];
    #pragma unroll
    for (int a = 0; a < 2; a++)
        #pragma unroll
        for (int b = 0; b < 8; b++)
            #pragma unroll
            for (int c = 0; c < 4; c++) acc[a][b][c] = 0.f;

    uint32_t a_row  = wm * 32 + (lane & 15);
    uint32_t a_col8 = (lane >> 4) * 8;
    uint32_t b_row  = wn * 64 + ((lane >> 4) & 1) * 8 + (lane & 7);
    uint32_t b_col8 = ((lane >> 3) & 1) * 8;

    int nc = K >> 5;
    gemm_load_stage(smb, 0, Ahi, Alo, Bhi, Blo, row0, col0, 0, M, K, tid);
    CP_COMMIT();

    for (int c = 0; c < nc; c++) {
        if (c + 1 < nc) {
            gemm_load_stage(smb, (c + 1) & 1, Ahi, Alo, Bhi, Blo,
                            row0, col0, (c + 1) << 5, M, K, tid);
            CP_COMMIT();
            CP_WAIT1();
        } else {
            CP_WAIT0();
        }
        __syncthreads();
        uint32_t sp = smb + (c & 1) * STAGEB;
        #pragma unroll
        for (int kk = 0; kk < 2; kk++) {
            uint32_t ah[2][4], al[2][4];
            #pragma unroll
            for (int mt = 0; mt < 2; mt++) {
                uint32_t off = (a_row + mt * 16) * PADB + (kk * 16 + a_col8) * 2;
                ldmat_x4(ah[mt], sp + SM_AH + off);
                ldmat_x4(al[mt], sp + SM_AL + off);
            }
            #pragma unroll
            for (int p = 0; p < 4; p++) {
                uint32_t bh[4], bl[4];
                uint32_t off = (b_row + p * 16) * PADB + (kk * 16 + b_col8) * 2;
                ldmat_x4(bh, sp + SM_BH + off);
                ldmat_x4(bl, sp + SM_BL + off);
                #pragma unroll
                for (int mt = 0; mt < 2; mt++) {
                    mma_bf16(acc[mt][p * 2 + 0], ah[mt], &bh[0]);
                    mma_bf16(acc[mt][p * 2 + 1], ah[mt], &bh[2]);
                    mma_bf16(acc[mt][p * 2 + 0], ah[mt], &bl[0]);
                    mma_bf16(acc[mt][p * 2 + 1], ah[mt], &bl[2]);
                    mma_bf16(acc[mt][p * 2 + 0], al[mt], &bh[0]);
                    mma_bf16(acc[mt][p * 2 + 1], al[mt], &bh[2]);
                }
            }
        }
        __syncthreads();
    }

    int g = lane >> 2, tg = lane & 3;
    #pragma unroll
    for (int mt = 0; mt < 2; mt++) {
        int r_hi = row0 + wm * 32 + mt * 16 + g;
        #pragma unroll
        for (int j = 0; j < 8; j++) {
            int cc = col0 + wn * 64 + j * 8 + tg * 2;
            float bx = bias[cc], by = bias[cc + 1];
            #pragma unroll
            for (int half = 0; half < 2; half++) {
                int r = r_hi + half * 8;
                if (r >= M) continue;
                float ox = acc[mt][j][half * 2 + 0] + bx;
                float oy = acc[mt][j][half * 2 + 1] + by;
                if (out_mode == 2) {
                    ox = gelu_f(ox); oy = gelu_f(oy);
                    __nv_bfloat16 hx, lx, hy, ly;
                    split_bf16(ox, hx, lx);
                    split_bf16(oy, hy, ly);
                    __nv_bfloat162 hv; hv.x = hx; hv.y = hy;
                    __nv_bfloat162 lv; lv.x = lx; lv.y = ly;
                    *(__nv_bfloat162*)&Chi[(size_t)r * N + cc] = hv;
                    *(__nv_bfloat162*)&Clo[(size_t)r * N + cc] = lv;
                } else {
                    float2 o; o.x = ox; o.y = oy;
                    *(float2*)&C[(size_t)r * N + cc] = o;
                }
            }
        }
    }
}

// -------- residual + LayerNorm: warp per node ---------------------------------
__global__ void k_lnres(const float* __restrict__ xin, const float* __restrict__ yin,
                        const float* __restrict__ g, const float* __restrict__ b,
                        float* __restrict__ xout,
                        __nv_bfloat16* __restrict__ outH, __nv_bfloat16* __restrict__ outL,
                        int n_nodes) {
    int w = (blockIdx.x * blockDim.x + threadIdx.x) >> 5;
    if (w >= n_nodes) return;
    int lane = threadIdx.x & 31;
    int off = w * DD + lane * 8;

    float4 va = *(const float4*)&xin[off];
    float4 vb = *(const float4*)&xin[off + 4];
    if (yin) {
        float4 ya = *(const float4*)&yin[off];
        float4 yb = *(const float4*)&yin[off + 4];
        va.x += ya.x; va.y += ya.y; va.z += ya.z; va.w += ya.w;
        vb.x += yb.x; vb.y += yb.y; vb.z += yb.z; vb.w += yb.w;
    }
    float sum = va.x + va.y + va.z + va.w + vb.x + vb.y + vb.z + vb.w;
    #pragma unroll
    for (int o = 16; o; o >>= 1) sum += __shfl_xor_sync(0xffffffffu, sum, o);
    float mean = sum * (1.0f / 256.0f);
    float d[8] = { va.x-mean, va.y-mean, va.z-mean, va.w-mean,
                   vb.x-mean, vb.y-mean, vb.z-mean, vb.w-mean };
    float vs = 0.f;
    #pragma unroll
    for (int q = 0; q < 8; q++) vs += d[q] * d[q];
    #pragma unroll
    for (int o = 16; o; o >>= 1) vs += __shfl_xor_sync(0xffffffffu, vs, o);
    float inv = rsqrtf(vs * (1.0f / 256.0f) + 1e-5f);

    float4 ga = *(const float4*)&g[lane * 8];
    float4 gb = *(const float4*)&g[lane * 8 + 4];
    float4 ba = *(const float4*)&b[lane * 8];
    float4 bb = *(const float4*)&b[lane * 8 + 4];
    float r[8];
    r[0] = d[0]*inv*ga.x + ba.x; r[1] = d[1]*inv*ga.y + ba.y;
    r[2] = d[2]*inv*ga.z + ba.z; r[3] = d[3]*inv*ga.w + ba.w;
    r[4] = d[4]*inv*gb.x + bb.x; r[5] = d[5]*inv*gb.y + bb.y;
    r[6] = d[6]*inv*gb.z + bb.z; r[7] = d[7]*inv*gb.w + bb.w;
    *(float4*)&xout[off]     = make_float4(r[0], r[1], r[2], r[3]);
    *(float4*)&xout[off + 4] = make_float4(r[4], r[5], r[6], r[7]);
    if (outH) {
        __nv_bfloat16 h[8], lo[8];
        #pragma unroll
        for (int q = 0; q < 8; q++) split_bf16(r[q], h[q], lo[q]);
        *(uint4*)&outH[off] = *(uint4*)h;
        *(uint4*)&outL[off] = *(uint4*)lo;
    }
}

// ---------------- host ---------------------------------------------------------
extern "C" void kernel_launch(void* const* d_in, const int* in_sizes, int n_in,
                              void* d_out, int out_size) {
    const float* x     = (const float*)d_in[0];
    const int*   ei    = (const int*)  d_in[1];
    const int*   etype = (const int*)  d_in[2];
    const int*   ntype = (const int*)  d_in[3];
    const float* WQ    = (const float*)d_in[4];
    const float* WK    = (const float*)d_in[5];
    const float* WV    = (const float*)d_in[6];
    const float* WE    = (const float*)d_in[7];
    const float* mu    = (const float*)d_in[8];
    const float* Wo    = (const float*)d_in[9];
    const float* bo    = (const float*)d_in[10];
    const float* ln1g  = (const float*)d_in[11];
    const float* ln1b  = (const float*)d_in[12];
    const float* ln2g  = (const float*)d_in[13];
    const float* ln2b  = (const float*)d_in[14];
    const float* w1    = (const float*)d_in[15];
    const float* b1    = (const float*)d_in[16];
    const float* w2    = (const float*)d_in[17];
    const float* b2    = (const float*)d_in[18];
    const float* outg  = (const float*)d_in[19];
    const float* outb  = (const float*)d_in[20];

    int N = in_sizes[0] / DD;
    int E = in_sizes[2];

    float *px, *py, *pwet;
    cudaGetSymbolAddress((void**)&px,   g_x);
    cudaGetSymbolAddress((void**)&py,   g_y);
    cudaGetSymbolAddress((void**)&pwet, g_WET);

    __nv_bfloat16 *pAggH, *pAggL, *pXH, *pXL, *pFH, *pFL;
    cudaGetSymbolAddress((void**)&pAggH, g_aggH);
    cudaGetSymbolAddress((void**)&pAggL, g_aggL);
    cudaGetSymbolAddress((void**)&pXH,   g_xH);
    cudaGetSymbolAddress((void**)&pXL,   g_xL);
    cudaGetSymbolAddress((void**)&pFH,   g_ffnH);
    cudaGetSymbolAddress((void**)&pFL,   g_ffnL);

    __nv_bfloat16 *pWoH, *pWoL, *pW1H, *pW1L, *pW2H, *pW2L;
    cudaGetSymbolAddress((void**)&pWoH, g_WoT_hi);
    cudaGetSymbolAddress((void**)&pWoL, g_WoT_lo);
    cudaGetSymbolAddress((void**)&pW1H, g_W1T_hi);
    cudaGetSymbolAddress((void**)&pW1L, g_W1T_lo);
    cudaGetSymbolAddress((void**)&pW2H, g_W2T_hi);
    cudaGetSymbolAddress((void**)&pW2L, g_W2T_lo);

    cudaFuncSetAttribute(k_gemm_mma, cudaFuncAttributeMaxDynamicSharedMemorySize, GEMM_SMEM);

    // preprocessing (3 launches)
    k_count<<<1250, 256>>>(x, ei, ntype, WE, Wo, w1, w2, N, E);
    k_scan<<<1, 1024>>>(N);
    k_scat<<<(E + 255) / 256, 256>>>(ei, etype, ntype, N, E);

    int mtiles = (N + 127) / 128;
    int lnblocks = (N + 7) / 8;

    for (int l = 0; l < LLAY; l++) {
        const float* wq  = WQ + (size_t)l * TNN * HH * 1024;
        const float* wk  = WK + (size_t)l * TNN * HH * 1024;
        const float* wv  = WV + (size_t)l * TNN * HH * 1024;
        const float* mul = mu + (size_t)l * HH * TEE;
        const float* bol = bo + (size_t)l * DD;
        const float* b1l = b1 + (size_t)l * FF;
        const float* b2l = b2 + (size_t)l * DD;
        const float* wetl = pwet + (size_t)l * TEE * HH * 1024;

        k_qkv<<<(N + NPB - 1) / NPB, 256>>>(wq, wk, wv, wetl, mul, ntype, N);
        k_attn<<<(N * 32 + 255) / 256, 256>>>(N);

        {
            dim3 grid(DD / 128, mtiles);
            k_gemm_mma<<<grid, 256, GEMM_SMEM>>>(pAggH, pAggL,
                pWoH + (size_t)l * DD * DD, pWoL + (size_t)l * DD * DD,
                bol, py, (__nv_bfloat16*)nullptr, (__nv_bfloat16*)nullptr,
                N, DD, DD, 0);
        }
        k_lnres<<<lnblocks, 256>>>(px, py, ln1g + l * DD, ln1b + l * DD, px, pXH, pXL, N);

        {
            dim3 grid(FF / 128, mtiles);
            k_gemm_mma<<<grid, 256, GEMM_SMEM>>>(pXH, pXL,
                pW1H + (size_t)l * FF * DD, pW1L + (size_t)l * FF * DD,
                b1l, (float*)nullptr, pFH, pFL, N, FF, DD, 2);
        }
        {
            dim3 grid(DD / 128, mtiles);
            k_gemm_mma<<<grid, 256, GEMM_SMEM>>>(pFH, pFL,
                pW2H + (size_t)l * DD * FF, pW2L + (size_t)l * DD * FF,
                b2l, py, (__nv_bfloat16*)nullptr, (__nv_bfloat16*)nullptr,
                N, DD, FF, 0);
        }
        k_lnres<<<lnblocks, 256>>>(px, py, ln2g + l * DD, ln2b + l * DD, px,
                                   (__nv_bfloat16*)nullptr, (__nv_bfloat16*)nullptr, N);
    }

    k_lnres<<<lnblocks, 256>>>(px, (const float*)nullptr, outg, outb, (float*)d_out,
                               (__nv_bfloat16*)nullptr, (__nv_bfloat16*)nullptr, N);
}

// round 16
// speedup vs baseline: 1.1626x; 1.0018x over previous
#include <cuda_runtime.h>
#include <cuda_bf16.h>
#include <math.h>
#include <stdint.h>

#define NMAX 20000
#define EMAX 320000
#define DD   256
#define HH   8
#define HDD  32
#define TEE  3
#define TNN  4
#define LLAY 3
#define FF   1024
#define NPB  8
#define DBK  64          // degree buckets for attn load balancing

// ---------------- scratch (device globals; zero-initialized at load) --------
__device__ float g_x   [NMAX*DD];
__device__ float g_KV  [NMAX*2*DD];
__device__ float g_QW  [NMAX*TEE*DD];
__device__ float g_y   [NMAX*DD];
__device__ int   g_rowptr[NMAX+1];
__device__ int   g_cursor[NMAX];      // zero at entry (re-zeroed by k_attn)
__device__ int   g_cpack [EMAX];
__device__ int   g_order [NMAX];      // type-sorted (for k_qkv)
__device__ int   g_aorder[NMAX];      // degree-sorted desc (for k_attn)
__device__ int   g_tcnt  [TNN];       // zero at entry (re-zeroed by k_qkv)
__device__ int   g_tcur  [TNN];
__device__ int   g_dcur  [DBK];       // degree-bucket cursors (set by k_scan)
__device__ float g_WET [LLAY*TEE*HH*HDD*HDD];

__device__ __nv_bfloat16 g_aggH[NMAX*DD];
__device__ __nv_bfloat16 g_aggL[NMAX*DD];
__device__ __nv_bfloat16 g_xH  [NMAX*DD];
__device__ __nv_bfloat16 g_xL  [NMAX*DD];
__device__ __nv_bfloat16 g_ffnH[NMAX*FF];
__device__ __nv_bfloat16 g_ffnL[NMAX*FF];

__device__ __nv_bfloat16 g_WoT_hi[LLAY*DD*DD];
__device__ __nv_bfloat16 g_WoT_lo[LLAY*DD*DD];
__device__ __nv_bfloat16 g_W1T_hi[LLAY*FF*DD];
__device__ __nv_bfloat16 g_W1T_lo[LLAY*FF*DD];
__device__ __nv_bfloat16 g_W2T_hi[LLAY*DD*FF];
__device__ __nv_bfloat16 g_W2T_lo[LLAY*DD*FF];

// ---------------- helpers ------------------------------------------------
__device__ __forceinline__ float gelu_f(float v) {
    return 0.5f * v * (1.0f + erff(v * 0.70710678118654752f));
}
__device__ __forceinline__ uint32_t smem_to_u32(const void* p) {
    uint32_t a;
    asm("{ .reg .u64 t; cvta.to.shared.u64 t, %1; cvt.u32.u64 %0, t; }" : "=r"(a) : "l"(p));
    return a;
}
__device__ __forceinline__ void ldmat_x4(uint32_t* r, uint32_t addr) {
    asm volatile("ldmatrix.sync.aligned.m8n8.x4.shared.b16 {%0,%1,%2,%3}, [%4];"
        : "=r"(r[0]), "=r"(r[1]), "=r"(r[2]), "=r"(r[3]) : "r"(addr));
}
__device__ __forceinline__ void mma_bf16(float* d, const uint32_t* a, const uint32_t* b) {
    asm volatile("mma.sync.aligned.m16n8k16.row.col.f32.bf16.bf16.f32 "
        "{%0,%1,%2,%3}, {%4,%5,%6,%7}, {%8,%9}, {%0,%1,%2,%3};"
        : "+f"(d[0]), "+f"(d[1]), "+f"(d[2]), "+f"(d[3])
        : "r"(a[0]), "r"(a[1]), "r"(a[2]), "r"(a[3]), "r"(b[0]), "r"(b[1]));
}
__device__ __forceinline__ void cp16z(uint32_t dst, const void* src, bool valid) {
    int sz = valid ? 16 : 0;
    asm volatile("cp.async.cg.shared.global [%0], [%1], 16, %2;"
        :: "r"(dst), "l"(src), "r"(sz));
}
#define CP_COMMIT()  asm volatile("cp.async.commit_group;" ::: "memory")
#define CP_WAIT1()   asm volatile("cp.async.wait_group 1;" ::: "memory")
#define CP_WAIT0()   asm volatile("cp.async.wait_group 0;" ::: "memory")

__device__ __forceinline__ void split_bf16(float v, __nv_bfloat16& h, __nv_bfloat16& l) {
    h = __float2bfloat16_rn(v);
    l = __float2bfloat16_rn(v - __bfloat162float(h));
}

// ======= preprocessing (3 launches) ===========================================
__device__ __forceinline__ void splitT_one(const float* W, __nv_bfloat16* hi,
                                           __nv_bfloat16* lo, int K, int N, int i) {
    int k = i / N, n = i % N;
    float w = W[i];
    __nv_bfloat16 h, l; split_bf16(w, h, l);
    hi[(size_t)n * K + k] = h;
    lo[(size_t)n * K + k] = l;
}

__global__ void k_count(const float* __restrict__ x,
                        const int* __restrict__ ei, const int* __restrict__ nt,
                        const float* __restrict__ WE, const float* __restrict__ Wo,
                        const float* __restrict__ w1, const float* __restrict__ w2,
                        int n, int E) {
    int gs = gridDim.x * blockDim.x;
    int gid = blockIdx.x * blockDim.x + threadIdx.x;
    for (int i = gid; i < n * DD / 4; i += gs)
        ((float4*)g_x)[i] = ((const float4*)x)[i];
    for (int i = gid; i < E; i += gs) atomicAdd(&g_cursor[ei[E + i]], 1);
    for (int i = gid; i < n; i += gs) atomicAdd(&g_tcnt[nt[i]], 1);
    for (int i = gid; i < LLAY * TEE * HH * HDD * HDD; i += gs) {
        int d = i & 31, e = (i >> 5) & 31, base = i >> 10;
        g_WET[i] = WE[(base << 10) + (d << 5) + e];
    }
    for (int i = gid; i < LLAY * DD * DD; i += gs) {
        int l = i / (DD * DD), j = i % (DD * DD);
        splitT_one(Wo + (size_t)l * DD * DD, g_WoT_hi + (size_t)l * DD * DD,
                   g_WoT_lo + (size_t)l * DD * DD, DD, DD, j);
    }
    for (int i = gid; i < LLAY * DD * FF; i += gs) {
        int l = i / (DD * FF), j = i % (DD * FF);
        splitT_one(w1 + (size_t)l * DD * FF, g_W1T_hi + (size_t)l * FF * DD,
                   g_W1T_lo + (size_t)l * FF * DD, DD, FF, j);
    }
    for (int i = gid; i < LLAY * FF * DD; i += gs) {
        int l = i / (FF * DD), j = i % (FF * DD);
        splitT_one(w2 + (size_t)l * FF * DD, g_W2T_hi + (size_t)l * DD * FF,
                   g_W2T_lo + (size_t)l * DD * FF, FF, DD, j);
    }
}

__global__ void k_scan(int n) {
    __shared__ int wsum[32];
    __shared__ int dhist[DBK];
    int t = threadIdx.x;
    int lane = t & 31, wid = t >> 5;
    int chunk = (n + 1023) / 1024;
    int start = t * chunk;
    int end = start + chunk; if (end > n) end = n;

    if (t < DBK) dhist[t] = 0;

    int s = 0;
    for (int j = start; j < end; j++) s += g_cursor[j];
    int ps = s;
    #pragma unroll
    for (int o = 1; o < 32; o <<= 1) {
        int v = __shfl_up_sync(0xffffffffu, ps, o);
        if (lane >= o) ps += v;
    }
    if (lane == 31) wsum[wid] = ps;
    __syncthreads();
    if (wid == 0) {
        int pv = wsum[lane];
        #pragma unroll
        for (int o = 1; o < 32; o <<= 1) {
            int u = __shfl_up_sync(0xffffffffu, pv, o);
            if (lane >= o) pv += u;
        }
        wsum[lane] = pv;
    }
    __syncthreads();
    int base = ps - s + ((wid > 0) ? wsum[wid - 1] : 0);
    int run = base;
    for (int j = start; j < end; j++) {
        int c = g_cursor[j];
        g_rowptr[j] = run;
        g_cursor[j] = run;
        run += c;
        int b = (c < DBK) ? c : (DBK - 1);
        atomicAdd(&dhist[b], 1);
    }
    if (t == 0) {
        g_rowptr[n] = wsum[31];
        int c = 0;
        for (int k = 0; k < TNN; k++) { g_tcur[k] = c; c += g_tcnt[k]; }
        int d = 0;
        for (int b = DBK - 1; b >= 0; b--) { g_dcur[b] = d; d += dhist[b]; }
    }
}

__global__ void k_scat(const int* __restrict__ ei, const int* __restrict__ et,
                       const int* __restrict__ nt, int n, int E) {
    int gs = gridDim.x * blockDim.x;
    int gid = blockIdx.x * blockDim.x + threadIdx.x;
    for (int i = gid; i < E; i += gs) {
        int dst = ei[E + i];
        int p = atomicAdd(&g_cursor[dst], 1);
        g_cpack[p] = ei[i] | (et[i] << 24);
    }
    for (int i = gid; i < n; i += gs) {
        int p = atomicAdd(&g_tcur[nt[i]], 1);
        g_order[p] = i;
        int deg = g_rowptr[i + 1] - g_rowptr[i];
        int b = (deg < DBK) ? deg : (DBK - 1);
        int q = atomicAdd(&g_dcur[b], 1);
        g_aorder[q] = i;
    }
}

// -------- per-node QKV + QW (R9 version, measured 86.5us/layer) ---------------
__global__ void __launch_bounds__(256) k_qkv(
    const float* __restrict__ wq, const float* __restrict__ wk,
    const float* __restrict__ wv, const float* __restrict__ wet_l,
    const float* __restrict__ mu_l, const int* __restrict__ ntype,
    int n_nodes) {
    __shared__ float xs [NPB][DD];
    __shared__ float qsh[NPB][DD];
    int t = threadIdx.x;
    if (blockIdx.x == 0 && t < TNN) { g_tcnt[t] = 0; g_tcur[t] = 0; }
    int slot0 = blockIdx.x * NPB;
    int nv = n_nodes - slot0; if (nv > NPB) nv = NPB;

    int nidx[NPB];
    #pragma unroll
    for (int ni = 0; ni < NPB; ni++) {
        int n = g_order[(ni < nv) ? (slot0 + ni) : slot0];
        nidx[ni] = n;
        xs[ni][t] = g_x[n * DD + t];
    }
    int tn0 = ntype[nidx[0]];
    bool uni = true;
    #pragma unroll
    for (int ni = 1; ni < NPB; ni++) uni &= (ntype[nidx[ni]] == tn0);
    __syncthreads();

    int v  = t & 63;
    int h  = v >> 3;
    int c4 = v & 7;

    if (t < 192) {
        int which = t >> 6;
        const float* Wb = (which == 0 ? wq : (which == 1 ? wk : wv));
        int off = h * 32 + c4 * 4;
        int kvoff = (which == 1) ? off : (off + DD);
        if (uni) {
            const float* W = Wb + ((tn0 * HH + h) << 10) + c4 * 4;
            float4 acc[NPB];
            #pragma unroll
            for (int ni = 0; ni < NPB; ni++) acc[ni] = make_float4(0.f, 0.f, 0.f, 0.f);
            #pragma unroll
            for (int d4 = 0; d4 < 8; d4++) {
                float4 w0 = *(const float4*)(W + ((d4 * 4 + 0) << 5));
                float4 w1 = *(const float4*)(W + ((d4 * 4 + 1) << 5));
                float4 w2 = *(const float4*)(W + ((d4 * 4 + 2) << 5));
                float4 w3 = *(const float4*)(W + ((d4 * 4 + 3) << 5));
                #pragma unroll
                for (int ni = 0; ni < NPB; ni++) {
                    float4 xv = *(const float4*)&xs[ni][h * 32 + d4 * 4];
                    acc[ni].x += xv.x*w0.x + xv.y*w1.x + xv.z*w2.x + xv.w*w3.x;
                    acc[ni].y += xv.x*w0.y + xv.y*w1.y + xv.z*w2.y + xv.w*w3.y;
                    acc[ni].z += xv.x*w0.z + xv.y*w1.z + xv.z*w2.z + xv.w*w3.z;
                    acc[ni].w += xv.x*w0.w + xv.y*w1.w + xv.z*w2.w + xv.w*w3.w;
                }
            }
            #pragma unroll
            for (int ni = 0; ni < NPB; ni++) {
                if (which == 0) *(float4*)&qsh[ni][off] = acc[ni];
                else            *(float4*)&g_KV[nidx[ni]*2*DD + kvoff] = acc[ni];
            }
        } else {
            #pragma unroll 1
            for (int ni = 0; ni < NPB; ni++) {
                int tn = ntype[nidx[ni]];
                const float* W = Wb + ((tn * HH + h) << 10) + c4 * 4;
                float4 a = make_float4(0.f, 0.f, 0.f, 0.f);
                #pragma unroll
                for (int d4 = 0; d4 < 8; d4++) {
                    float4 w0 = *(const float4*)(W + ((d4 * 4 + 0) << 5));
                    float4 w1 = *(const float4*)(W + ((d4 * 4 + 1) << 5));
                    float4 w2 = *(const float4*)(W + ((d4 * 4 + 2) << 5));
                    float4 w3 = *(const float4*)(W + ((d4 * 4 + 3) << 5));
                    float4 xv = *(const float4*)&xs[ni][h * 32 + d4 * 4];
                    a.x += xv.x*w0.x + xv.y*w1.x + xv.z*w2.x + xv.w*w3.x;
                    a.y += xv.x*w0.y + xv.y*w1.y + xv.z*w2.y + xv.w*w3.y;
                    a.z += xv.x*w0.z + xv.y*w1.z + xv.z*w2.z + xv.w*w3.z;
                    a.w += xv.x*w0.w + xv.y*w1.w + xv.z*w2.w + xv.w*w3.w;
                }
                if (which == 0) *(float4*)&qsh[ni][off] = a;
                else            *(float4*)&g_KV[nidx[ni]*2*DD + kvoff] = a;
            }
        }
    }
    __syncthreads();

    if (t < 192) {
        int et = t >> 6;
        const float* W = wet_l + ((et * HH + h) << 10) + c4 * 4;
        float c = mu_l[h * TEE + et] * 0.17677669529663687f;
        float4 acc[NPB];
        #pragma unroll
        for (int ni = 0; ni < NPB; ni++) acc[ni] = make_float4(0.f, 0.f, 0.f, 0.f);
        #pragma unroll
        for (int e4 = 0; e4 < 8; e4++) {
            float4 w0 = *(const float4*)(W + ((e4 * 4 + 0) << 5));
            float4 w1 = *(const float4*)(W + ((e4 * 4 + 1) << 5));
            float4 w2 = *(const float4*)(W + ((e4 * 4 + 2) << 5));
            float4 w3 = *(const float4*)(W + ((e4 * 4 + 3) << 5));
            #pragma unroll
            for (int ni = 0; ni < NPB; ni++) {
                float4 xv = *(const float4*)&qsh[ni][h * 32 + e4 * 4];
                acc[ni].x += xv.x*w0.x + xv.y*w1.x + xv.z*w2.x + xv.w*w3.x;
                acc[ni].y += xv.x*w0.y + xv.y*w1.y + xv.z*w2.y + xv.w*w3.y;
                acc[ni].z += xv.x*w0.z + xv.y*w1.z + xv.z*w2.z + xv.w*w3.z;
                acc[ni].w += xv.x*w0.w + xv.y*w1.w + xv.z*w2.w + xv.w*w3.w;
            }
        }
        int off = h * 32 + c4 * 4;
        #pragma unroll
        for (int ni = 0; ni < NPB; ni++) {
            float4 o;
            o.x = acc[ni].x * c; o.y = acc[ni].y * c;
            o.z = acc[ni].z * c; o.w = acc[ni].w * c;
            *(float4*)&g_QW[(nidx[ni] * TEE + et) * DD + off] = o;
        }
    }
}

// -------- edge attention: degree-sorted assignment, 6-edge unrolled -----------
__device__ __forceinline__ float edge_score(int pk, int base,
    const float4& q0a, const float4& q0b, const float4& q1a, const float4& q1b,
    const float4& q2a, const float4& q2b, float4& va, float4& vb) {
    int src = pk & 0xFFFFFF;
    int et  = pk >> 24;
    const float* kp = &g_KV[src * 2 * DD + base];
    float4 ka = *(const float4*)kp, kb = *(const float4*)(kp + 4);
    va = *(const float4*)(kp + DD); vb = *(const float4*)(kp + DD + 4);
    float4 qa = (et == 0) ? q0a : ((et == 1) ? q1a : q2a);
    float4 qb = (et == 0) ? q0b : ((et == 1) ? q1b : q2b);
    float p = ka.x*qa.x + ka.y*qa.y + ka.z*qa.z + ka.w*qa.w
            + kb.x*qb.x + kb.y*qb.y + kb.z*qb.z + kb.w*qb.w;
    p += __shfl_xor_sync(0xffffffffu, p, 1);
    p += __shfl_xor_sync(0xffffffffu, p, 2);
    return p;
}

__global__ void __launch_bounds__(256, 2) k_attn(int n_nodes) {
    int slot = (blockIdx.x * blockDim.x + threadIdx.x) >> 5;
    if (slot >= n_nodes) return;
    int w = g_aorder[slot];
    int l = threadIdx.x & 31;
    if (l == 0) g_cursor[w] = 0;
    int base = ((l >> 2) << 5) + ((l & 3) << 3);

    const float* qwp = &g_QW[(w * 3) * DD + base];
    float4 q0a = *(const float4*)(qwp);
    float4 q0b = *(const float4*)(qwp + 4);
    float4 q1a = *(const float4*)(qwp + DD);
    float4 q1b = *(const float4*)(qwp + DD + 4);
    float4 q2a = *(const float4*)(qwp + 2 * DD);
    float4 q2b = *(const float4*)(qwp + 2 * DD + 4);

    float m = -1e30f, s = 0.f;
    float a0=0,a1=0,a2=0,a3=0,a4=0,a5=0,a6=0,a7=0;
    int r0 = g_rowptr[w], r1 = g_rowptr[w + 1];
    int i = r0;
    for (; i + 6 <= r1; i += 6) {
        int pk0 = g_cpack[i],   pk1 = g_cpack[i+1], pk2 = g_cpack[i+2];
        int pk3 = g_cpack[i+3], pk4 = g_cpack[i+4], pk5 = g_cpack[i+5];
        float4 v0a,v0b,v1a,v1b,v2a,v2b,v3a,v3b,v4a,v4b,v5a,v5b;
        float p0 = edge_score(pk0, base, q0a,q0b,q1a,q1b,q2a,q2b, v0a, v0b);
        float p1 = edge_score(pk1, base, q0a,q0b,q1a,q1b,q2a,q2b, v1a, v1b);
        float p2 = edge_score(pk2, base, q0a,q0b,q1a,q1b,q2a,q2b, v2a, v2b);
        float p3 = edge_score(pk3, base, q0a,q0b,q1a,q1b,q2a,q2b, v3a, v3b);
        float p4 = edge_score(pk4, base, q0a,q0b,q1a,q1b,q2a,q2b, v4a, v4b);
        float p5 = edge_score(pk5, base, q0a,q0b,q1a,q1b,q2a,q2b, v5a, v5b);
        float mn = fmaxf(m, fmaxf(fmaxf(fmaxf(p0, p1), fmaxf(p2, p3)), fmaxf(p4, p5)));
        float f  = __expf(m - mn);
        float e0 = __expf(p0 - mn);
        float e1 = __expf(p1 - mn);
        float e2 = __expf(p2 - mn);
        float e3 = __expf(p3 - mn);
        float e4 = __expf(p4 - mn);
        float e5 = __expf(p5 - mn);
        m = mn;
        s = s * f + ((e0 + e1) + (e2 + e3)) + (e4 + e5);
        a0 = a0*f + e0*v0a.x + e1*v1a.x + e2*v2a.x + e3*v3a.x + e4*v4a.x + e5*v5a.x;
        a1 = a1*f + e0*v0a.y + e1*v1a.y + e2*v2a.y + e3*v3a.y + e4*v4a.y + e5*v5a.y;
        a2 = a2*f + e0*v0a.z + e1*v1a.z + e2*v2a.z + e3*v3a.z + e4*v4a.z + e5*v5a.z;
        a3 = a3*f + e0*v0a.w + e1*v1a.w + e2*v2a.w + e3*v3a.w + e4*v4a.w + e5*v5a.w;
        a4 = a4*f + e0*v0b.x + e1*v1b.x + e2*v2b.x + e3*v3b.x + e4*v4b.x + e5*v5b.x;
        a5 = a5*f + e0*v0b.y + e1*v1b.y + e2*v2b.y + e3*v3b.y + e4*v4b.y + e5*v5b.y;
        a6 = a6*f + e0*v0b.z + e1*v1b.z + e2*v2b.z + e3*v3b.z + e4*v4b.z + e5*v5b.z;
        a7 = a7*f + e0*v0b.w + e1*v1b.w + e2*v2b.w + e3*v3b.w + e4*v4b.w + e5*v5b.w;
    }
    for (; i + 2 <= r1; i += 2) {
        int pk0 = g_cpack[i], pk1 = g_cpack[i+1];
        float4 v0a, v0b, v1a, v1b;
        float p0 = edge_score(pk0, base, q0a,q0b,q1a,q1b,q2a,q2b, v0a, v0b);
        float p1 = edge_score(pk1, base, q0a,q0b,q1a,q1b,q2a,q2b, v1a, v1b);
        float mn = fmaxf(m, fmaxf(p0, p1));
        float f  = __expf(m - mn);
        float e0 = __expf(p0 - mn);
        float e1 = __expf(p1 - mn);
        m = mn;
        s = s * f + e0 + e1;
        a0 = a0*f + e0*v0a.x + e1*v1a.x;  a1 = a1*f + e0*v0a.y + e1*v1a.y;
        a2 = a2*f + e0*v0a.z + e1*v1a.z;  a3 = a3*f + e0*v0a.w + e1*v1a.w;
        a4 = a4*f + e0*v0b.x + e1*v1b.x;  a5 = a5*f + e0*v0b.y + e1*v1b.y;
        a6 = a6*f + e0*v0b.z + e1*v1b.z;  a7 = a7*f + e0*v0b.w + e1*v1b.w;
    }
    for (; i < r1; i++) {
        float4 va, vb;
        float p = edge_score(g_cpack[i], base, q0a,q0b,q1a,q1b,q2a,q2b, va, vb);
        float mn = fmaxf(m, p);
        float f  = __expf(m - mn);
        float e  = __expf(p - mn);
        m = mn;
        s = s * f + e;
        a0 = a0*f + e*va.x; a1 = a1*f + e*va.y; a2 = a2*f + e*va.z; a3 = a3*f + e*va.w;
        a4 = a4*f + e*vb.x; a5 = a5*f + e*vb.y; a6 = a6*f + e*vb.z; a7 = a7*f + e*vb.w;
    }
    float inv = 1.0f / (s + 1e-10f);
    float o[8] = { a0*inv, a1*inv, a2*inv, a3*inv, a4*inv, a5*inv, a6*inv, a7*inv };
    __nv_bfloat16 h[8], lo[8];
    #pragma unroll
    for (int q = 0; q < 8; q++) split_bf16(o[q], h[q], lo[q]);
    *(uint4*)&g_aggH[w * DD + base] = *(uint4*)h;
    *(uint4*)&g_aggL[w * DD + base] = *(uint4*)lo;
}

// ============== pipelined tensor-core GEMM (bf16x3, cp.async) ================
#define PADB  80
#define TILEB 10240
#define SM_AH 0
#define SM_AL (TILEB)
#define SM_BH (2*TILEB)
#define SM_BL (3*TILEB)
#define STAGEB (4*TILEB)
#define GEMM_SMEM (2*STAGEB)

__device__ __forceinline__ void gemm_load_stage(
    uint32_t smb, int stage,
    const __nv_bfloat16* __restrict__ Ahi, const __nv_bfloat16* __restrict__ Alo,
    const __nv_bfloat16* __restrict__ Bhi, const __nv_bfloat16* __restrict__ Blo,
    int row0, int col0, int k0, int M, int K, int tid)
{
    uint32_t sp = smb + stage * STAGEB;
    #pragma unroll
    for (int it = 0; it < 2; it++) {
        int idx = tid + it * 256;
        int row = idx >> 2, seg = idx & 3;
        uint32_t off = row * PADB + seg * 16;
        size_t goff = (size_t)(row0 + row) * K + k0 + seg * 8;
        bool v = (row0 + row) < M;
        cp16z(sp + SM_AH + off, Ahi + goff, v);
        cp16z(sp + SM_AL + off, Alo + goff, v);
    }
    #pragma unroll
    for (int it = 0; it < 2; it++) {
        int idx = tid + it * 256;
        int n = idx >> 2, seg = idx & 3;
        uint32_t off = n * PADB + seg * 16;
        size_t goff = (size_t)(col0 + n) * K + k0 + seg * 8;
        cp16z(sp + SM_BH + off, Bhi + goff, true);
        cp16z(sp + SM_BL + off, Blo + goff, true);
    }
}

__global__ void __launch_bounds__(256, 2) k_gemm_mma(
    const __nv_bfloat16* __restrict__ Ahi, const __nv_bfloat16* __restrict__ Alo,
    const __nv_bfloat16* __restrict__ Bhi, const __nv_bfloat16* __restrict__ Blo,
    const float* __restrict__ bias, float* __restrict__ C,
    __nv_bfloat16* __restrict__ Chi, __nv_bfloat16* __restrict__ Clo,
    int M, int N, int K, int out_mode)
{
    extern __shared__ __align__(16) char smem[];
    uint32_t smb = smem_to_u32(smem);
    int tid = threadIdx.x, wid = tid >> 5, lane = tid & 31;
    int row0 = blockIdx.y * 128, col0 = blockIdx.x * 128;
    int wm = wid & 3, wn = wid >> 2;

    float acc[2][8][4];
    #pragma unroll
    for (int a = 0; a < 2; a++)
        #pragma unroll
        for (int b = 0; b < 8; b++)
            #pragma unroll
            for (int c = 0; c < 4; c++) acc[a][b][c] = 0.f;

    uint32_t a_row  = wm * 32 + (lane & 15);
    uint32_t a_col8 = (lane >> 4) * 8;
    uint32_t b_row  = wn * 64 + ((lane >> 4) & 1) * 8 + (lane & 7);
    uint32_t b_col8 = ((lane >> 3) & 1) * 8;

    int nc = K >> 5;
    gemm_load_stage(smb, 0, Ahi, Alo, Bhi, Blo, row0, col0, 0, M, K, tid);
    CP_COMMIT();

    for (int c = 0; c < nc; c++) {
        if (c + 1 < nc) {
            gemm_load_stage(smb, (c + 1) & 1, Ahi, Alo, Bhi, Blo,
                            row0, col0, (c + 1) << 5, M, K, tid);
            CP_COMMIT();
            CP_WAIT1();
        } else {
            CP_WAIT0();
        }
        __syncthreads();
        uint32_t sp = smb + (c & 1) * STAGEB;
        #pragma unroll
        for (int kk = 0; kk < 2; kk++) {
            uint32_t ah[2][4], al[2][4];
            #pragma unroll
            for (int mt = 0; mt < 2; mt++) {
                uint32_t off = (a_row + mt * 16) * PADB + (kk * 16 + a_col8) * 2;
                ldmat_x4(ah[mt], sp + SM_AH + off);
                ldmat_x4(al[mt], sp + SM_AL + off);
            }
            #pragma unroll
            for (int p = 0; p < 4; p++) {
                uint32_t bh[4], bl[4];
                uint32_t off = (b_row + p * 16) * PADB + (kk * 16 + b_col8) * 2;
                ldmat_x4(bh, sp + SM_BH + off);
                ldmat_x4(bl, sp + SM_BL + off);
                #pragma unroll
                for (int mt = 0; mt < 2; mt++) {
                    mma_bf16(acc[mt][p * 2 + 0], ah[mt], &bh[0]);
                    mma_bf16(acc[mt][p * 2 + 1], ah[mt], &bh[2]);
                    mma_bf16(acc[mt][p * 2 + 0], ah[mt], &bl[0]);
                    mma_bf16(acc[mt][p * 2 + 1], ah[mt], &bl[2]);
                    mma_bf16(acc[mt][p * 2 + 0], al[mt], &bh[0]);
                    mma_bf16(acc[mt][p * 2 + 1], al[mt], &bh[2]);
                }
            }
        }
        __syncthreads();
    }

    int g = lane >> 2, tg = lane & 3;
    #pragma unroll
    for (int mt = 0; mt < 2; mt++) {
        int r_hi = row0 + wm * 32 + mt * 16 + g;
        #pragma unroll
        for (int j = 0; j < 8; j++) {
            int cc = col0 + wn * 64 + j * 8 + tg * 2;
            float bx = bias[cc], by = bias[cc + 1];
            #pragma unroll
            for (int half = 0; half < 2; half++) {
                int r = r_hi + half * 8;
                if (r >= M) continue;
                float ox = acc[mt][j][half * 2 + 0] + bx;
                float oy = acc[mt][j][half * 2 + 1] + by;
                if (out_mode == 2) {
                    ox = gelu_f(ox); oy = gelu_f(oy);
                    __nv_bfloat16 hx, lx, hy, ly;
                    split_bf16(ox, hx, lx);
                    split_bf16(oy, hy, ly);
                    __nv_bfloat162 hv; hv.x = hx; hv.y = hy;
                    __nv_bfloat162 lv; lv.x = lx; lv.y = ly;
                    *(__nv_bfloat162*)&Chi[(size_t)r * N + cc] = hv;
                    *(__nv_bfloat162*)&Clo[(size_t)r * N + cc] = lv;
                } else {
                    float2 o; o.x = ox; o.y = oy;
                    *(float2*)&C[(size_t)r * N + cc] = o;
                }
            }
        }
    }
}

// -------- residual + LayerNorm: warp per node ---------------------------------
__global__ void k_lnres(const float* __restrict__ xin, const float* __restrict__ yin,
                        const float* __restrict__ g, const float* __restrict__ b,
                        float* __restrict__ xout,
                        __nv_bfloat16* __restrict__ outH, __nv_bfloat16* __restrict__ outL,
                        int n_nodes) {
    int w = (blockIdx.x * blockDim.x + threadIdx.x) >> 5;
    if (w >= n_nodes) return;
    int lane = threadIdx.x & 31;
    int off = w * DD + lane * 8;

    float4 va = *(const float4*)&xin[off];
    float4 vb = *(const float4*)&xin[off + 4];
    if (yin) {
        float4 ya = *(const float4*)&yin[off];
        float4 yb = *(const float4*)&yin[off + 4];
        va.x += ya.x; va.y += ya.y; va.z += ya.z; va.w += ya.w;
        vb.x += yb.x; vb.y += yb.y; vb.z += yb.z; vb.w += yb.w;
    }
    float sum = va.x + va.y + va.z + va.w + vb.x + vb.y + vb.z + vb.w;
    #pragma unroll
    for (int o = 16; o; o >>= 1) sum += __shfl_xor_sync(0xffffffffu, sum, o);
    float mean = sum * (1.0f / 256.0f);
    float d[8] = { va.x-mean, va.y-mean, va.z-mean, va.w-mean,
                   vb.x-mean, vb.y-mean, vb.z-mean, vb.w-mean };
    float vs = 0.f;
    #pragma unroll
    for (int q = 0; q < 8; q++) vs += d[q] * d[q];
    #pragma unroll
    for (int o = 16; o; o >>= 1) vs += __shfl_xor_sync(0xffffffffu, vs, o);
    float inv = rsqrtf(vs * (1.0f / 256.0f) + 1e-5f);

    float4 ga = *(const float4*)&g[lane * 8];
    float4 gb = *(const float4*)&g[lane * 8 + 4];
    float4 ba = *(const float4*)&b[lane * 8];
    float4 bb = *(const float4*)&b[lane * 8 + 4];
    float r[8];
    r[0] = d[0]*inv*ga.x + ba.x; r[1] = d[1]*inv*ga.y + ba.y;
    r[2] = d[2]*inv*ga.z + ba.z; r[3] = d[3]*inv*ga.w + ba.w;
    r[4] = d[4]*inv*gb.x + bb.x; r[5] = d[5]*inv*gb.y + bb.y;
    r[6] = d[6]*inv*gb.z + bb.z; r[7] = d[7]*inv*gb.w + bb.w;
    *(float4*)&xout[off]     = make_float4(r[0], r[1], r[2], r[3]);
    *(float4*)&xout[off + 4] = make_float4(r[4], r[5], r[6], r[7]);
    if (outH) {
        __nv_bfloat16 h[8], lo[8];
        #pragma unroll
        for (int q = 0; q < 8; q++) split_bf16(r[q], h[q], lo[q]);
        *(uint4*)&outH[off] = *(uint4*)h;
        *(uint4*)&outL[off] = *(uint4*)lo;
    }
}

// ---------------- host ---------------------------------------------------------
extern "C" void kernel_launch(void* const* d_in, const int* in_sizes, int n_in,
                              void* d_out, int out_size) {
    const float* x     = (const float*)d_in[0];
    const int*   ei    = (const int*)  d_in[1];
    const int*   etype = (const int*)  d_in[2];
    const int*   ntype = (const int*)  d_in[3];
    const float* WQ    = (const float*)d_in[4];
    const float* WK    = (const float*)d_in[5];
    const float* WV    = (const float*)d_in[6];
    const float* WE    = (const float*)d_in[7];
    const float* mu    = (const float*)d_in[8];
    const float* Wo    = (const float*)d_in[9];
    const float* bo    = (const float*)d_in[10];
    const float* ln1g  = (const float*)d_in[11];
    const float* ln1b  = (const float*)d_in[12];
    const float* ln2g  = (const float*)d_in[13];
    const float* ln2b  = (const float*)d_in[14];
    const float* w1    = (const float*)d_in[15];
    const float* b1    = (const float*)d_in[16];
    const float* w2    = (const float*)d_in[17];
    const float* b2    = (const float*)d_in[18];
    const float* outg  = (const float*)d_in[19];
    const float* outb  = (const float*)d_in[20];

    int N = in_sizes[0] / DD;
    int E = in_sizes[2];

    float *px, *py, *pwet;
    cudaGetSymbolAddress((void**)&px,   g_x);
    cudaGetSymbolAddress((void**)&py,   g_y);
    cudaGetSymbolAddress((void**)&pwet, g_WET);

    __nv_bfloat16 *pAggH, *pAggL, *pXH, *pXL, *pFH, *pFL;
    cudaGetSymbolAddress((void**)&pAggH, g_aggH);
    cudaGetSymbolAddress((void**)&pAggL, g_aggL);
    cudaGetSymbolAddress((void**)&pXH,   g_xH);
    cudaGetSymbolAddress((void**)&pXL,   g_xL);
    cudaGetSymbolAddress((void**)&pFH,   g_ffnH);
    cudaGetSymbolAddress((void**)&pFL,   g_ffnL);

    __nv_bfloat16 *pWoH, *pWoL, *pW1H, *pW1L, *pW2H, *pW2L;
    cudaGetSymbolAddress((void**)&pWoH, g_WoT_hi);
    cudaGetSymbolAddress((void**)&pWoL, g_WoT_lo);
    cudaGetSymbolAddress((void**)&pW1H, g_W1T_hi);
    cudaGetSymbolAddress((void**)&pW1L, g_W1T_lo);
    cudaGetSymbolAddress((void**)&pW2H, g_W2T_hi);
    cudaGetSymbolAddress((void**)&pW2L, g_W2T_lo);

    cudaFuncSetAttribute(k_gemm_mma, cudaFuncAttributeMaxDynamicSharedMemorySize, GEMM_SMEM);

    // preprocessing (3 launches)
    k_count<<<1250, 256>>>(x, ei, ntype, WE, Wo, w1, w2, N, E);
    k_scan<<<1, 1024>>>(N);
    k_scat<<<(E + 255) / 256, 256>>>(ei, etype, ntype, N, E);

    int mtiles = (N + 127) / 128;
    int lnblocks = (N + 7) / 8;

    for (int l = 0; l < LLAY; l++) {
        const float* wq  = WQ + (size_t)l * TNN * HH * 1024;
        const float* wk  = WK + (size_t)l * TNN * HH * 1024;
        const float* wv  = WV + (size_t)l * TNN * HH * 1024;
        const float* mul = mu + (size_t)l * HH * TEE;
        const float* bol = bo + (size_t)l * DD;
        const float* b1l = b1 + (size_t)l * FF;
        const float* b2l = b2 + (size_t)l * DD;
        const float* wetl = pwet + (size_t)l * TEE * HH * 1024;

        k_qkv<<<(N + NPB - 1) / NPB, 256>>>(wq, wk, wv, wetl, mul, ntype, N);
        k_attn<<<(N * 32 + 255) / 256, 256>>>(N);

        {
            dim3 grid(DD / 128, mtiles);
            k_gemm_mma<<<grid, 256, GEMM_SMEM>>>(pAggH, pAggL,
                pWoH + (size_t)l * DD * DD, pWoL + (size_t)l * DD * DD,
                bol, py, (__nv_bfloat16*)nullptr, (__nv_bfloat16*)nullptr,
                N, DD, DD, 0);
        }
        k_lnres<<<lnblocks, 256>>>(px, py, ln1g + l * DD, ln1b + l * DD, px, pXH, pXL, N);

        {
            dim3 grid(FF / 128, mtiles);
            k_gemm_mma<<<grid, 256, GEMM_SMEM>>>(pXH, pXL,
                pW1H + (size_t)l * FF * DD, pW1L + (size_t)l * FF * DD,
                b1l, (float*)nullptr, pFH, pFL, N, FF, DD, 2);
        }
        {
            dim3 grid(DD / 128, mtiles);
            k_gemm_mma<<<grid, 256, GEMM_SMEM>>>(pFH, pFL,
                pW2H + (size_t)l * DD * FF, pW2L + (size_t)l * DD * FF,
                b2l, py, (__nv_bfloat16*)nullptr, (__nv_bfloat16*)nullptr,
                N, DD, FF, 0);
        }
        k_lnres<<<lnblocks, 256>>>(px, py, ln2g + l * DD, ln2b + l * DD, px,
                                   (__nv_bfloat16*)nullptr, (__nv_bfloat16*)nullptr, N);
    }

    k_lnres<<<lnblocks, 256>>>(px, (const float*)nullptr, outg, outb, (float*)d_out,
                               (__nv_bfloat16*)nullptr, (__nv_bfloat16*)nullptr, N);
}

// round 17
// speedup vs baseline: 1.1994x; 1.0317x over previous
#include <cuda_runtime.h>
#include <cuda_bf16.h>
#include <math.h>
#include <stdint.h>

#define NMAX 20000
#define EMAX 320000
#define DD   256
#define HH   8
#define HDD  32
#define TEE  3
#define TNN  4
#define LLAY 3
#define FF   1024
#define NPB  8
#define DBK  64          // degree buckets for attn load balancing

// ---------------- scratch (device globals; zero-initialized at load) --------
__device__ float g_x   [NMAX*DD];
__device__ float g_KV  [NMAX*2*DD];
__device__ float g_QW  [NMAX*TEE*DD];
__device__ float g_y   [NMAX*DD];
__device__ float g_y2  [NMAX*DD];
__device__ int   g_rowptr[NMAX+1];
__device__ int   g_cursor[NMAX];      // zero at entry (re-zeroed by k_attn)
__device__ int   g_cpack [EMAX];
__device__ int   g_order [NMAX];      // type-sorted (for k_qkv)
__device__ int   g_aorder[NMAX];      // degree-sorted desc (for k_attn)
__device__ int   g_tcnt  [TNN];       // zero at entry (re-zeroed by k_qkv)
__device__ int   g_tcur  [TNN];
__device__ int   g_dcur  [DBK];       // degree-bucket cursors (set by k_scan)
__device__ float g_WET [LLAY*TEE*HH*HDD*HDD];

__device__ __nv_bfloat16 g_aggH[NMAX*DD];
__device__ __nv_bfloat16 g_aggL[NMAX*DD];
__device__ __nv_bfloat16 g_xH  [NMAX*DD];
__device__ __nv_bfloat16 g_xL  [NMAX*DD];
__device__ __nv_bfloat16 g_ffnH[NMAX*FF];
__device__ __nv_bfloat16 g_ffnL[NMAX*FF];

__device__ __nv_bfloat16 g_WoT_hi[LLAY*DD*DD];
__device__ __nv_bfloat16 g_WoT_lo[LLAY*DD*DD];
__device__ __nv_bfloat16 g_W1T_hi[LLAY*FF*DD];
__device__ __nv_bfloat16 g_W1T_lo[LLAY*FF*DD];
__device__ __nv_bfloat16 g_W2T_hi[LLAY*DD*FF];
__device__ __nv_bfloat16 g_W2T_lo[LLAY*DD*FF];

// ---------------- helpers ------------------------------------------------
__device__ __forceinline__ float gelu_f(float v) {
    return 0.5f * v * (1.0f + erff(v * 0.70710678118654752f));
}
__device__ __forceinline__ uint32_t smem_to_u32(const void* p) {
    uint32_t a;
    asm("{ .reg .u64 t; cvta.to.shared.u64 t, %1; cvt.u32.u64 %0, t; }" : "=r"(a) : "l"(p));
    return a;
}
__device__ __forceinline__ void ldmat_x4(uint32_t* r, uint32_t addr) {
    asm volatile("ldmatrix.sync.aligned.m8n8.x4.shared.b16 {%0,%1,%2,%3}, [%4];"
        : "=r"(r[0]), "=r"(r[1]), "=r"(r[2]), "=r"(r[3]) : "r"(addr));
}
__device__ __forceinline__ void mma_bf16(float* d, const uint32_t* a, const uint32_t* b) {
    asm volatile("mma.sync.aligned.m16n8k16.row.col.f32.bf16.bf16.f32 "
        "{%0,%1,%2,%3}, {%4,%5,%6,%7}, {%8,%9}, {%0,%1,%2,%3};"
        : "+f"(d[0]), "+f"(d[1]), "+f"(d[2]), "+f"(d[3])
        : "r"(a[0]), "r"(a[1]), "r"(a[2]), "r"(a[3]), "r"(b[0]), "r"(b[1]));
}
__device__ __forceinline__ void cp16z(uint32_t dst, const void* src, bool valid) {
    int sz = valid ? 16 : 0;
    asm volatile("cp.async.cg.shared.global [%0], [%1], 16, %2;"
        :: "r"(dst), "l"(src), "r"(sz));
}
#define CP_COMMIT()  asm volatile("cp.async.commit_group;" ::: "memory")
#define CP_WAIT1()   asm volatile("cp.async.wait_group 1;" ::: "memory")
#define CP_WAIT0()   asm volatile("cp.async.wait_group 0;" ::: "memory")

__device__ __forceinline__ void split_bf16(float v, __nv_bfloat16& h, __nv_bfloat16& l) {
    h = __float2bfloat16_rn(v);
    l = __float2bfloat16_rn(v - __bfloat162float(h));
}

// ======= preprocessing (3 launches) ===========================================
__device__ __forceinline__ void splitT_one(const float* W, __nv_bfloat16* hi,
                                           __nv_bfloat16* lo, int K, int N, int i) {
    int k = i / N, n = i % N;
    float w = W[i];
    __nv_bfloat16 h, l; split_bf16(w, h, l);
    hi[(size_t)n * K + k] = h;
    lo[(size_t)n * K + k] = l;
}

__global__ void k_count(const float* __restrict__ x,
                        const int* __restrict__ ei, const int* __restrict__ nt,
                        const float* __restrict__ WE, const float* __restrict__ Wo,
                        const float* __restrict__ w1, const float* __restrict__ w2,
                        int n, int E) {
    int gs = gridDim.x * blockDim.x;
    int gid = blockIdx.x * blockDim.x + threadIdx.x;
    for (int i = gid; i < n * DD / 4; i += gs)
        ((float4*)g_x)[i] = ((const float4*)x)[i];
    for (int i = gid; i < E; i += gs) atomicAdd(&g_cursor[ei[E + i]], 1);
    for (int i = gid; i < n; i += gs) atomicAdd(&g_tcnt[nt[i]], 1);
    for (int i = gid; i < LLAY * TEE * HH * HDD * HDD; i += gs) {
        int d = i & 31, e = (i >> 5) & 31, base = i >> 10;
        g_WET[i] = WE[(base << 10) + (d << 5) + e];
    }
    for (int i = gid; i < LLAY * DD * DD; i += gs) {
        int l = i / (DD * DD), j = i % (DD * DD);
        splitT_one(Wo + (size_t)l * DD * DD, g_WoT_hi + (size_t)l * DD * DD,
                   g_WoT_lo + (size_t)l * DD * DD, DD, DD, j);
    }
    for (int i = gid; i < LLAY * DD * FF; i += gs) {
        int l = i / (DD * FF), j = i % (DD * FF);
        splitT_one(w1 + (size_t)l * DD * FF, g_W1T_hi + (size_t)l * FF * DD,
                   g_W1T_lo + (size_t)l * FF * DD, DD, FF, j);
    }
    for (int i = gid; i < LLAY * FF * DD; i += gs) {
        int l = i / (FF * DD), j = i % (FF * DD);
        splitT_one(w2 + (size_t)l * FF * DD, g_W2T_hi + (size_t)l * DD * FF,
                   g_W2T_lo + (size_t)l * DD * FF, FF, DD, j);
    }
}

__global__ void k_scan(int n) {
    __shared__ int wsum[32];
    __shared__ int dhist[DBK];
    int t = threadIdx.x;
    int lane = t & 31, wid = t >> 5;
    int chunk = (n + 1023) / 1024;
    int start = t * chunk;
    int end = start + chunk; if (end > n) end = n;

    if (t < DBK) dhist[t] = 0;

    int s = 0;
    for (int j = start; j < end; j++) s += g_cursor[j];
    int ps = s;
    #pragma unroll
    for (int o = 1; o < 32; o <<= 1) {
        int v = __shfl_up_sync(0xffffffffu, ps, o);
        if (lane >= o) ps += v;
    }
    if (lane == 31) wsum[wid] = ps;
    __syncthreads();
    if (wid == 0) {
        int pv = wsum[lane];
        #pragma unroll
        for (int o = 1; o < 32; o <<= 1) {
            int u = __shfl_up_sync(0xffffffffu, pv, o);
            if (lane >= o) pv += u;
        }
        wsum[lane] = pv;
    }
    __syncthreads();
    int base = ps - s + ((wid > 0) ? wsum[wid - 1] : 0);
    int run = base;
    for (int j = start; j < end; j++) {
        int c = g_cursor[j];
        g_rowptr[j] = run;
        g_cursor[j] = run;
        run += c;
        int b = (c < DBK) ? c : (DBK - 1);
        atomicAdd(&dhist[b], 1);
    }
    if (t == 0) {
        g_rowptr[n] = wsum[31];
        int c = 0;
        for (int k = 0; k < TNN; k++) { g_tcur[k] = c; c += g_tcnt[k]; }
        int d = 0;
        for (int b = DBK - 1; b >= 0; b--) { g_dcur[b] = d; d += dhist[b]; }
    }
}

__global__ void k_scat(const int* __restrict__ ei, const int* __restrict__ et,
                       const int* __restrict__ nt, int n, int E) {
    int gs = gridDim.x * blockDim.x;
    int gid = blockIdx.x * blockDim.x + threadIdx.x;
    for (int i = gid; i < E; i += gs) {
        int dst = ei[E + i];
        int p = atomicAdd(&g_cursor[dst], 1);
        g_cpack[p] = ei[i] | (et[i] << 24);
    }
    for (int i = gid; i < n; i += gs) {
        int p = atomicAdd(&g_tcur[nt[i]], 1);
        g_order[p] = i;
        int deg = g_rowptr[i + 1] - g_rowptr[i];
        int b = (deg < DBK) ? deg : (DBK - 1);
        int q = atomicAdd(&g_dcur[b], 1);
        g_aorder[q] = i;
    }
}

// -------- per-node QKV + QW (R9 version, measured 86.5us/layer) ---------------
__global__ void __launch_bounds__(256) k_qkv(
    const float* __restrict__ wq, const float* __restrict__ wk,
    const float* __restrict__ wv, const float* __restrict__ wet_l,
    const float* __restrict__ mu_l, const int* __restrict__ ntype,
    int n_nodes) {
    __shared__ float xs [NPB][DD];
    __shared__ float qsh[NPB][DD];
    int t = threadIdx.x;
    if (blockIdx.x == 0 && t < TNN) { g_tcnt[t] = 0; g_tcur[t] = 0; }
    int slot0 = blockIdx.x * NPB;
    int nv = n_nodes - slot0; if (nv > NPB) nv = NPB;

    int nidx[NPB];
    #pragma unroll
    for (int ni = 0; ni < NPB; ni++) {
        int n = g_order[(ni < nv) ? (slot0 + ni) : slot0];
        nidx[ni] = n;
        xs[ni][t] = g_x[n * DD + t];
    }
    int tn0 = ntype[nidx[0]];
    bool uni = true;
    #pragma unroll
    for (int ni = 1; ni < NPB; ni++) uni &= (ntype[nidx[ni]] == tn0);
    __syncthreads();

    int v  = t & 63;
    int h  = v >> 3;
    int c4 = v & 7;

    if (t < 192) {
        int which = t >> 6;
        const float* Wb = (which == 0 ? wq : (which == 1 ? wk : wv));
        int off = h * 32 + c4 * 4;
        int kvoff = (which == 1) ? off : (off + DD);
        if (uni) {
            const float* W = Wb + ((tn0 * HH + h) << 10) + c4 * 4;
            float4 acc[NPB];
            #pragma unroll
            for (int ni = 0; ni < NPB; ni++) acc[ni] = make_float4(0.f, 0.f, 0.f, 0.f);
            #pragma unroll
            for (int d4 = 0; d4 < 8; d4++) {
                float4 w0 = *(const float4*)(W + ((d4 * 4 + 0) << 5));
                float4 w1 = *(const float4*)(W + ((d4 * 4 + 1) << 5));
                float4 w2 = *(const float4*)(W + ((d4 * 4 + 2) << 5));
                float4 w3 = *(const float4*)(W + ((d4 * 4 + 3) << 5));
                #pragma unroll
                for (int ni = 0; ni < NPB; ni++) {
                    float4 xv = *(const float4*)&xs[ni][h * 32 + d4 * 4];
                    acc[ni].x += xv.x*w0.x + xv.y*w1.x + xv.z*w2.x + xv.w*w3.x;
                    acc[ni].y += xv.x*w0.y + xv.y*w1.y + xv.z*w2.y + xv.w*w3.y;
                    acc[ni].z += xv.x*w0.z + xv.y*w1.z + xv.z*w2.z + xv.w*w3.z;
                    acc[ni].w += xv.x*w0.w + xv.y*w1.w + xv.z*w2.w + xv.w*w3.w;
                }
            }
            #pragma unroll
            for (int ni = 0; ni < NPB; ni++) {
                if (which == 0) *(float4*)&qsh[ni][off] = acc[ni];
                else            *(float4*)&g_KV[nidx[ni]*2*DD + kvoff] = acc[ni];
            }
        } else {
            #pragma unroll 1
            for (int ni = 0; ni < NPB; ni++) {
                int tn = ntype[nidx[ni]];
                const float* W = Wb + ((tn * HH + h) << 10) + c4 * 4;
                float4 a = make_float4(0.f, 0.f, 0.f, 0.f);
                #pragma unroll
                for (int d4 = 0; d4 < 8; d4++) {
                    float4 w0 = *(const float4*)(W + ((d4 * 4 + 0) << 5));
                    float4 w1 = *(const float4*)(W + ((d4 * 4 + 1) << 5));
                    float4 w2 = *(const float4*)(W + ((d4 * 4 + 2) << 5));
                    float4 w3 = *(const float4*)(W + ((d4 * 4 + 3) << 5));
                    float4 xv = *(const float4*)&xs[ni][h * 32 + d4 * 4];
                    a.x += xv.x*w0.x + xv.y*w1.x + xv.z*w2.x + xv.w*w3.x;
                    a.y += xv.x*w0.y + xv.y*w1.y + xv.z*w2.y + xv.w*w3.y;
                    a.z += xv.x*w0.z + xv.y*w1.z + xv.z*w2.z + xv.w*w3.z;
                    a.w += xv.x*w0.w + xv.y*w1.w + xv.z*w2.w + xv.w*w3.w;
                }
                if (which == 0) *(float4*)&qsh[ni][off] = a;
                else            *(float4*)&g_KV[nidx[ni]*2*DD + kvoff] = a;
            }
        }
    }
    __syncthreads();

    if (t < 192) {
        int et = t >> 6;
        const float* W = wet_l + ((et * HH + h) << 10) + c4 * 4;
        float c = mu_l[h * TEE + et] * 0.17677669529663687f;
        float4 acc[NPB];
        #pragma unroll
        for (int ni = 0; ni < NPB; ni++) acc[ni] = make_float4(0.f, 0.f, 0.f, 0.f);
        #pragma unroll
        for (int e4 = 0; e4 < 8; e4++) {
            float4 w0 = *(const float4*)(W + ((e4 * 4 + 0) << 5));
            float4 w1 = *(const float4*)(W + ((e4 * 4 + 1) << 5));
            float4 w2 = *(const float4*)(W + ((e4 * 4 + 2) << 5));
            float4 w3 = *(const float4*)(W + ((e4 * 4 + 3) << 5));
            #pragma unroll
            for (int ni = 0; ni < NPB; ni++) {
                float4 xv = *(const float4*)&qsh[ni][h * 32 + e4 * 4];
                acc[ni].x += xv.x*w0.x + xv.y*w1.x + xv.z*w2.x + xv.w*w3.x;
                acc[ni].y += xv.x*w0.y + xv.y*w1.y + xv.z*w2.y + xv.w*w3.y;
                acc[ni].z += xv.x*w0.z + xv.y*w1.z + xv.z*w2.z + xv.w*w3.z;
                acc[ni].w += xv.x*w0.w + xv.y*w1.w + xv.z*w2.w + xv.w*w3.w;
            }
        }
        int off = h * 32 + c4 * 4;
        #pragma unroll
        for (int ni = 0; ni < NPB; ni++) {
            float4 o;
            o.x = acc[ni].x * c; o.y = acc[ni].y * c;
            o.z = acc[ni].z * c; o.w = acc[ni].w * c;
            *(float4*)&g_QW[(nidx[ni] * TEE + et) * DD + off] = o;
        }
    }
}

// -------- edge attention: degree-sorted assignment, 6-edge unrolled -----------
__device__ __forceinline__ float edge_score(int pk, int base,
    const float4& q0a, const float4& q0b, const float4& q1a, const float4& q1b,
    const float4& q2a, const float4& q2b, float4& va, float4& vb) {
    int src = pk & 0xFFFFFF;
    int et  = pk >> 24;
    const float* kp = &g_KV[src * 2 * DD + base];
    float4 ka = *(const float4*)kp, kb = *(const float4*)(kp + 4);
    va = *(const float4*)(kp + DD); vb = *(const float4*)(kp + DD + 4);
    float4 qa = (et == 0) ? q0a : ((et == 1) ? q1a : q2a);
    float4 qb = (et == 0) ? q0b : ((et == 1) ? q1b : q2b);
    float p = ka.x*qa.x + ka.y*qa.y + ka.z*qa.z + ka.w*qa.w
            + kb.x*qb.x + kb.y*qb.y + kb.z*qb.z + kb.w*qb.w;
    p += __shfl_xor_sync(0xffffffffu, p, 1);
    p += __shfl_xor_sync(0xffffffffu, p, 2);
    return p;
}

__global__ void __launch_bounds__(256, 2) k_attn(int n_nodes) {
    int slot = (blockIdx.x * blockDim.x + threadIdx.x) >> 5;
    if (slot >= n_nodes) return;
    int w = g_aorder[slot];
    int l = threadIdx.x & 31;
    if (l == 0) g_cursor[w] = 0;
    int base = ((l >> 2) << 5) + ((l & 3) << 3);

    const float* qwp = &g_QW[(w * 3) * DD + base];
    float4 q0a = *(const float4*)(qwp);
    float4 q0b = *(const float4*)(qwp + 4);
    float4 q1a = *(const float4*)(qwp + DD);
    float4 q1b = *(const float4*)(qwp + DD + 4);
    float4 q2a = *(const float4*)(qwp + 2 * DD);
    float4 q2b = *(const float4*)(qwp + 2 * DD + 4);

    float m = -1e30f, s = 0.f;
    float a0=0,a1=0,a2=0,a3=0,a4=0,a5=0,a6=0,a7=0;
    int r0 = g_rowptr[w], r1 = g_rowptr[w + 1];
    int i = r0;
    for (; i + 6 <= r1; i += 6) {
        int pk0 = g_cpack[i],   pk1 = g_cpack[i+1], pk2 = g_cpack[i+2];
        int pk3 = g_cpack[i+3], pk4 = g_cpack[i+4], pk5 = g_cpack[i+5];
        float4 v0a,v0b,v1a,v1b,v2a,v2b,v3a,v3b,v4a,v4b,v5a,v5b;
        float p0 = edge_score(pk0, base, q0a,q0b,q1a,q1b,q2a,q2b, v0a, v0b);
        float p1 = edge_score(pk1, base, q0a,q0b,q1a,q1b,q2a,q2b, v1a, v1b);
        float p2 = edge_score(pk2, base, q0a,q0b,q1a,q1b,q2a,q2b, v2a, v2b);
        float p3 = edge_score(pk3, base, q0a,q0b,q1a,q1b,q2a,q2b, v3a, v3b);
        float p4 = edge_score(pk4, base, q0a,q0b,q1a,q1b,q2a,q2b, v4a, v4b);
        float p5 = edge_score(pk5, base, q0a,q0b,q1a,q1b,q2a,q2b, v5a, v5b);
        float mn = fmaxf(m, fmaxf(fmaxf(fmaxf(p0, p1), fmaxf(p2, p3)), fmaxf(p4, p5)));
        float f  = __expf(m - mn);
        float e0 = __expf(p0 - mn);
        float e1 = __expf(p1 - mn);
        float e2 = __expf(p2 - mn);
        float e3 = __expf(p3 - mn);
        float e4 = __expf(p4 - mn);
        float e5 = __expf(p5 - mn);
        m = mn;
        s = s * f + ((e0 + e1) + (e2 + e3)) + (e4 + e5);
        a0 = a0*f + e0*v0a.x + e1*v1a.x + e2*v2a.x + e3*v3a.x + e4*v4a.x + e5*v5a.x;
        a1 = a1*f + e0*v0a.y + e1*v1a.y + e2*v2a.y + e3*v3a.y + e4*v4a.y + e5*v5a.y;
        a2 = a2*f + e0*v0a.z + e1*v1a.z + e2*v2a.z + e3*v3a.z + e4*v4a.z + e5*v5a.z;
        a3 = a3*f + e0*v0a.w + e1*v1a.w + e2*v2a.w + e3*v3a.w + e4*v4a.w + e5*v5a.w;
        a4 = a4*f + e0*v0b.x + e1*v1b.x + e2*v2b.x + e3*v3b.x + e4*v4b.x + e5*v5b.x;
        a5 = a5*f + e0*v0b.y + e1*v1b.y + e2*v2b.y + e3*v3b.y + e4*v4b.y + e5*v5b.y;
        a6 = a6*f + e0*v0b.z + e1*v1b.z + e2*v2b.z + e3*v3b.z + e4*v4b.z + e5*v5b.z;
        a7 = a7*f + e0*v0b.w + e1*v1b.w + e2*v2b.w + e3*v3b.w + e4*v4b.w + e5*v5b.w;
    }
    for (; i + 2 <= r1; i += 2) {
        int pk0 = g_cpack[i], pk1 = g_cpack[i+1];
        float4 v0a, v0b, v1a, v1b;
        float p0 = edge_score(pk0, base, q0a,q0b,q1a,q1b,q2a,q2b, v0a, v0b);
        float p1 = edge_score(pk1, base, q0a,q0b,q1a,q1b,q2a,q2b, v1a, v1b);
        float mn = fmaxf(m, fmaxf(p0, p1));
        float f  = __expf(m - mn);
        float e0 = __expf(p0 - mn);
        float e1 = __expf(p1 - mn);
        m = mn;
        s = s * f + e0 + e1;
        a0 = a0*f + e0*v0a.x + e1*v1a.x;  a1 = a1*f + e0*v0a.y + e1*v1a.y;
        a2 = a2*f + e0*v0a.z + e1*v1a.z;  a3 = a3*f + e0*v0a.w + e1*v1a.w;
        a4 = a4*f + e0*v0b.x + e1*v1b.x;  a5 = a5*f + e0*v0b.y + e1*v1b.y;
        a6 = a6*f + e0*v0b.z + e1*v1b.z;  a7 = a7*f + e0*v0b.w + e1*v1b.w;
    }
    for (; i < r1; i++) {
        float4 va, vb;
        float p = edge_score(g_cpack[i], base, q0a,q0b,q1a,q1b,q2a,q2b, va, vb);
        float mn = fmaxf(m, p);
        float f  = __expf(m - mn);
        float e  = __expf(p - mn);
        m = mn;
        s = s * f + e;
        a0 = a0*f + e*va.x; a1 = a1*f + e*va.y; a2 = a2*f + e*va.z; a3 = a3*f + e*va.w;
        a4 = a4*f + e*vb.x; a5 = a5*f + e*vb.y; a6 = a6*f + e*vb.z; a7 = a7*f + e*vb.w;
    }
    float inv = 1.0f / (s + 1e-10f);
    float o[8] = { a0*inv, a1*inv, a2*inv, a3*inv, a4*inv, a5*inv, a6*inv, a7*inv };
    __nv_bfloat16 h[8], lo[8];
    #pragma unroll
    for (int q = 0; q < 8; q++) split_bf16(o[q], h[q], lo[q]);
    *(uint4*)&g_aggH[w * DD + base] = *(uint4*)h;
    *(uint4*)&g_aggL[w * DD + base] = *(uint4*)lo;
}

// ============== pipelined tensor-core GEMM (bf16x3, cp.async) ================
// split-K: gridDim.z halves the K range; z=0 writes C (+bias), z=1 writes C2.
#define PADB  80
#define TILEB 10240
#define SM_AH 0
#define SM_AL (TILEB)
#define SM_BH (2*TILEB)
#define SM_BL (3*TILEB)
#define STAGEB (4*TILEB)
#define GEMM_SMEM (2*STAGEB)

__device__ __forceinline__ void gemm_load_stage(
    uint32_t smb, int stage,
    const __nv_bfloat16* __restrict__ Ahi, const __nv_bfloat16* __restrict__ Alo,
    const __nv_bfloat16* __restrict__ Bhi, const __nv_bfloat16* __restrict__ Blo,
    int row0, int col0, int k0, int M, int Kstride, int tid)
{
    uint32_t sp = smb + stage * STAGEB;
    #pragma unroll
    for (int it = 0; it < 2; it++) {
        int idx = tid + it * 256;
        int row = idx >> 2, seg = idx & 3;
        uint32_t off = row * PADB + seg * 16;
        size_t goff = (size_t)(row0 + row) * Kstride + k0 + seg * 8;
        bool v = (row0 + row) < M;
        cp16z(sp + SM_AH + off, Ahi + goff, v);
        cp16z(sp + SM_AL + off, Alo + goff, v);
    }
    #pragma unroll
    for (int it = 0; it < 2; it++) {
        int idx = tid + it * 256;
        int n = idx >> 2, seg = idx & 3;
        uint32_t off = n * PADB + seg * 16;
        size_t goff = (size_t)(col0 + n) * Kstride + k0 + seg * 8;
        cp16z(sp + SM_BH + off, Bhi + goff, true);
        cp16z(sp + SM_BL + off, Blo + goff, true);
    }
}

__global__ void __launch_bounds__(256, 2) k_gemm_mma(
    const __nv_bfloat16* __restrict__ Ahi, const __nv_bfloat16* __restrict__ Alo,
    const __nv_bfloat16* __restrict__ Bhi, const __nv_bfloat16* __restrict__ Blo,
    const float* __restrict__ bias, float* __restrict__ C, float* __restrict__ C2,
    __nv_bfloat16* __restrict__ Chi, __nv_bfloat16* __restrict__ Clo,
    int M, int N, int Ksub, int Kstride, int out_mode)
{
    extern __shared__ __align__(16) char smem[];
    uint32_t smb = smem_to_u32(smem);
    int tid = threadIdx.x, wid = tid >> 5, lane = tid & 31;
    int row0 = blockIdx.y * 128, col0 = blockIdx.x * 128;
    int kbase = blockIdx.z * Ksub;
    int wm = wid & 3, wn = wid >> 2;

    float acc[2][8][4];
    #pragma unroll
    for (int a = 0; a < 2; a++)
        #pragma unroll
        for (int b = 0; b < 8; b++)
            #pragma unroll
            for (int c = 0; c < 4; c++) acc[a][b][c] = 0.f;

    uint32_t a_row  = wm * 32 + (lane & 15);
    uint32_t a_col8 = (lane >> 4) * 8;
    uint32_t b_row  = wn * 64 + ((lane >> 4) & 1) * 8 + (lane & 7);
    uint32_t b_col8 = ((lane >> 3) & 1) * 8;

    int nc = Ksub >> 5;
    gemm_load_stage(smb, 0, Ahi, Alo, Bhi, Blo, row0, col0, kbase, M, Kstride, tid);
    CP_COMMIT();

    for (int c = 0; c < nc; c++) {
        if (c + 1 < nc) {
            gemm_load_stage(smb, (c + 1) & 1, Ahi, Alo, Bhi, Blo,
                            row0, col0, kbase + ((c + 1) << 5), M, Kstride, tid);
            CP_COMMIT();
            CP_WAIT1();
        } else {
            CP_WAIT0();
        }
        __syncthreads();
        uint32_t sp = smb + (c & 1) * STAGEB;
        #pragma unroll
        for (int kk = 0; kk < 2; kk++) {
            uint32_t ah[2][4], al[2][4];
            #pragma unroll
            for (int mt = 0; mt < 2; mt++) {
                uint32_t off = (a_row + mt * 16) * PADB + (kk * 16 + a_col8) * 2;
                ldmat_x4(ah[mt], sp + SM_AH + off);
                ldmat_x4(al[mt], sp + SM_AL + off);
            }
            #pragma unroll
            for (int p = 0; p < 4; p++) {
                uint32_t bh[4], bl[4];
                uint32_t off = (b_row + p * 16) * PADB + (kk * 16 + b_col8) * 2;
                ldmat_x4(bh, sp + SM_BH + off);
                ldmat_x4(bl, sp + SM_BL + off);
                #pragma unroll
                for (int mt = 0; mt < 2; mt++) {
                    mma_bf16(acc[mt][p * 2 + 0], ah[mt], &bh[0]);
                    mma_bf16(acc[mt][p * 2 + 1], ah[mt], &bh[2]);
                    mma_bf16(acc[mt][p * 2 + 0], ah[mt], &bl[0]);
                    mma_bf16(acc[mt][p * 2 + 1], ah[mt], &bl[2]);
                    mma_bf16(acc[mt][p * 2 + 0], al[mt], &bh[0]);
                    mma_bf16(acc[mt][p * 2 + 1], al[mt], &bh[2]);
                }
            }
        }
        __syncthreads();
    }

    int g = lane >> 2, tg = lane & 3;
    float* Cout = (blockIdx.z == 0) ? C : C2;
    #pragma unroll
    for (int mt = 0; mt < 2; mt++) {
        int r_hi = row0 + wm * 32 + mt * 16 + g;
        #pragma unroll
        for (int j = 0; j < 8; j++) {
            int cc = col0 + wn * 64 + j * 8 + tg * 2;
            float bx = (blockIdx.z == 0) ? bias[cc]     : 0.f;
            float by = (blockIdx.z == 0) ? bias[cc + 1] : 0.f;
            #pragma unroll
            for (int half = 0; half < 2; half++) {
                int r = r_hi + half * 8;
                if (r >= M) continue;
                float ox = acc[mt][j][half * 2 + 0] + bx;
                float oy = acc[mt][j][half * 2 + 1] + by;
                if (out_mode == 2) {
                    ox = gelu_f(ox); oy = gelu_f(oy);
                    __nv_bfloat16 hx, lx, hy, ly;
                    split_bf16(ox, hx, lx);
                    split_bf16(oy, hy, ly);
                    __nv_bfloat162 hv; hv.x = hx; hv.y = hy;
                    __nv_bfloat162 lv; lv.x = lx; lv.y = ly;
                    *(__nv_bfloat162*)&Chi[(size_t)r * N + cc] = hv;
                    *(__nv_bfloat162*)&Clo[(size_t)r * N + cc] = lv;
                } else {
                    float2 o; o.x = ox; o.y = oy;
                    *(float2*)&Cout[(size_t)r * N + cc] = o;
                }
            }
        }
    }
}

// -------- residual + LayerNorm: warp per node (optional 2nd partial) ----------
__global__ void k_lnres(const float* __restrict__ xin, const float* __restrict__ yin,
                        const float* __restrict__ yin2,
                        const float* __restrict__ g, const float* __restrict__ b,
                        float* __restrict__ xout,
                        __nv_bfloat16* __restrict__ outH, __nv_bfloat16* __restrict__ outL,
                        int n_nodes) {
    int w = (blockIdx.x * blockDim.x + threadIdx.x) >> 5;
    if (w >= n_nodes) return;
    int lane = threadIdx.x & 31;
    int off = w * DD + lane * 8;

    float4 va = *(const float4*)&xin[off];
    float4 vb = *(const float4*)&xin[off + 4];
    if (yin) {
        float4 ya = *(const float4*)&yin[off];
        float4 yb = *(const float4*)&yin[off + 4];
        va.x += ya.x; va.y += ya.y; va.z += ya.z; va.w += ya.w;
        vb.x += yb.x; vb.y += yb.y; vb.z += yb.z; vb.w += yb.w;
    }
    if (yin2) {
        float4 ya = *(const float4*)&yin2[off];
        float4 yb = *(const float4*)&yin2[off + 4];
        va.x += ya.x; va.y += ya.y; va.z += ya.z; va.w += ya.w;
        vb.x += yb.x; vb.y += yb.y; vb.z += yb.z; vb.w += yb.w;
    }
    float sum = va.x + va.y + va.z + va.w + vb.x + vb.y + vb.z + vb.w;
    #pragma unroll
    for (int o = 16; o; o >>= 1) sum += __shfl_xor_sync(0xffffffffu, sum, o);
    float mean = sum * (1.0f / 256.0f);
    float d[8] = { va.x-mean, va.y-mean, va.z-mean, va.w-mean,
                   vb.x-mean, vb.y-mean, vb.z-mean, vb.w-mean };
    float vs = 0.f;
    #pragma unroll
    for (int q = 0; q < 8; q++) vs += d[q] * d[q];
    #pragma unroll
    for (int o = 16; o; o >>= 1) vs += __shfl_xor_sync(0xffffffffu, vs, o);
    float inv = rsqrtf(vs * (1.0f / 256.0f) + 1e-5f);

    float4 ga = *(const float4*)&g[lane * 8];
    float4 gb = *(const float4*)&g[lane * 8 + 4];
    float4 ba = *(const float4*)&b[lane * 8];
    float4 bb = *(const float4*)&b[lane * 8 + 4];
    float r[8];
    r[0] = d[0]*inv*ga.x + ba.x; r[1] = d[1]*inv*ga.y + ba.y;
    r[2] = d[2]*inv*ga.z + ba.z; r[3] = d[3]*inv*ga.w + ba.w;
    r[4] = d[4]*inv*gb.x + bb.x; r[5] = d[5]*inv*gb.y + bb.y;
    r[6] = d[6]*inv*gb.z + bb.z; r[7] = d[7]*inv*gb.w + bb.w;
    *(float4*)&xout[off]     = make_float4(r[0], r[1], r[2], r[3]);
    *(float4*)&xout[off + 4] = make_float4(r[4], r[5], r[6], r[7]);
    if (outH) {
        __nv_bfloat16 h[8], lo[8];
        #pragma unroll
        for (int q = 0; q < 8; q++) split_bf16(r[q], h[q], lo[q]);
        *(uint4*)&outH[off] = *(uint4*)h;
        *(uint4*)&outL[off] = *(uint4*)lo;
    }
}

// ---------------- host ---------------------------------------------------------
extern "C" void kernel_launch(void* const* d_in, const int* in_sizes, int n_in,
                              void* d_out, int out_size) {
    const float* x     = (const float*)d_in[0];
    const int*   ei    = (const int*)  d_in[1];
    const int*   etype = (const int*)  d_in[2];
    const int*   ntype = (const int*)  d_in[3];
    const float* WQ    = (const float*)d_in[4];
    const float* WK    = (const float*)d_in[5];
    const float* WV    = (const float*)d_in[6];
    const float* WE    = (const float*)d_in[7];
    const float* mu    = (const float*)d_in[8];
    const float* Wo    = (const float*)d_in[9];
    const float* bo    = (const float*)d_in[10];
    const float* ln1g  = (const float*)d_in[11];
    const float* ln1b  = (const float*)d_in[12];
    const float* ln2g  = (const float*)d_in[13];
    const float* ln2b  = (const float*)d_in[14];
    const float* w1    = (const float*)d_in[15];
    const float* b1    = (const float*)d_in[16];
    const float* w2    = (const float*)d_in[17];
    const float* b2    = (const float*)d_in[18];
    const float* outg  = (const float*)d_in[19];
    const float* outb  = (const float*)d_in[20];

    int N = in_sizes[0] / DD;
    int E = in_sizes[2];

    float *px, *py, *py2, *pwet;
    cudaGetSymbolAddress((void**)&px,   g_x);
    cudaGetSymbolAddress((void**)&py,   g_y);
    cudaGetSymbolAddress((void**)&py2,  g_y2);
    cudaGetSymbolAddress((void**)&pwet, g_WET);

    __nv_bfloat16 *pAggH, *pAggL, *pXH, *pXL, *pFH, *pFL;
    cudaGetSymbolAddress((void**)&pAggH, g_aggH);
    cudaGetSymbolAddress((void**)&pAggL, g_aggL);
    cudaGetSymbolAddress((void**)&pXH,   g_xH);
    cudaGetSymbolAddress((void**)&pXL,   g_xL);
    cudaGetSymbolAddress((void**)&pFH,   g_ffnH);
    cudaGetSymbolAddress((void**)&pFL,   g_ffnL);

    __nv_bfloat16 *pWoH, *pWoL, *pW1H, *pW1L, *pW2H, *pW2L;
    cudaGetSymbolAddress((void**)&pWoH, g_WoT_hi);
    cudaGetSymbolAddress((void**)&pWoL, g_WoT_lo);
    cudaGetSymbolAddress((void**)&pW1H, g_W1T_hi);
    cudaGetSymbolAddress((void**)&pW1L, g_W1T_lo);
    cudaGetSymbolAddress((void**)&pW2H, g_W2T_hi);
    cudaGetSymbolAddress((void**)&pW2L, g_W2T_lo);

    cudaFuncSetAttribute(k_gemm_mma, cudaFuncAttributeMaxDynamicSharedMemorySize, GEMM_SMEM);

    // preprocessing (3 launches)
    k_count<<<1250, 256>>>(x, ei, ntype, WE, Wo, w1, w2, N, E);
    k_scan<<<1, 1024>>>(N);
    k_scat<<<(E + 255) / 256, 256>>>(ei, etype, ntype, N, E);

    int mtiles = (N + 127) / 128;
    int lnblocks = (N + 7) / 8;

    for (int l = 0; l < LLAY; l++) {
        const float* wq  = WQ + (size_t)l * TNN * HH * 1024;
        const float* wk  = WK + (size_t)l * TNN * HH * 1024;
        const float* wv  = WV + (size_t)l * TNN * HH * 1024;
        const float* mul = mu + (size_t)l * HH * TEE;
        const float* bol = bo + (size_t)l * DD;
        const float* b1l = b1 + (size_t)l * FF;
        const float* b2l = b2 + (size_t)l * DD;
        const float* wetl = pwet + (size_t)l * TEE * HH * 1024;

        k_qkv<<<(N + NPB - 1) / NPB, 256>>>(wq, wk, wv, wetl, mul, ntype, N);
        k_attn<<<(N * 32 + 255) / 256, 256>>>(N);

        // Wo GEMM, split-K (2 halves of 128): y + y2
        {
            dim3 grid(DD / 128, mtiles, 2);
            k_gemm_mma<<<grid, 256, GEMM_SMEM>>>(pAggH, pAggL,
                pWoH + (size_t)l * DD * DD, pWoL + (size_t)l * DD * DD,
                bol, py, py2, (__nv_bfloat16*)nullptr, (__nv_bfloat16*)nullptr,
                N, DD, 128, DD, 0);
        }
        k_lnres<<<lnblocks, 256>>>(px, py, py2, ln1g + l * DD, ln1b + l * DD,
                                   px, pXH, pXL, N);

        // w1 GEMM: full K=256, no split (GELU -> bf16 hi/lo)
        {
            dim3 grid(FF / 128, mtiles, 1);
            k_gemm_mma<<<grid, 256, GEMM_SMEM>>>(pXH, pXL,
                pW1H + (size_t)l * FF * DD, pW1L + (size_t)l * FF * DD,
                b1l, (float*)nullptr, (float*)nullptr, pFH, pFL,
                N, FF, DD, DD, 2);
        }
        // w2 GEMM, split-K (2 halves of 512): y + y2
        {
            dim3 grid(DD / 128, mtiles, 2);
            k_gemm_mma<<<grid, 256, GEMM_SMEM>>>(pFH, pFL,
                pW2H + (size_t)l * DD * FF, pW2L + (size_t)l * DD * FF,
                b2l, py, py2, (__nv_bfloat16*)nullptr, (__nv_bfloat16*)nullptr,
                N, DD, 512, FF, 0);
        }
        k_lnres<<<lnblocks, 256>>>(px, py, py2, ln2g + l * DD, ln2b + l * DD, px,
                                   (__nv_bfloat16*)nullptr, (__nv_bfloat16*)nullptr, N);
    }

    k_lnres<<<lnblocks, 256>>>(px, (const float*)nullptr, (const float*)nullptr,
                               outg, outb, (float*)d_out,
                               (__nv_bfloat16*)nullptr, (__nv_bfloat16*)nullptr, N);
}